// round 13
// baseline (speedup 1.0000x reference)
#include <cuda_runtime.h>
#include <cuda_bf16.h>
#include <cstdint>

// ============================================================================
// Graph_ODE_RNN — 8-launch pipeline; R8 pool GEMM (Kc=64) + gcnf with
// Wt-smem aliased into cat buffer (higher occupancy):
//  [csr+splitA+Wt] -> gcn1 -> pool1 -> gcnf1 -> pool2 -> gcnf2 -> pool3 -> head
// ============================================================================

#define TT 200

// ---------------- static scratch (no allocation allowed) -------------------
__device__ float g_p1[2 * 512 * 16 * TT];
__device__ float g_p2[2 * 128 * 32 * TT];
__device__ float g_p3[2 * 64 * 64 * TT];

__device__ __nv_bfloat16 g_A1h[512 * 2048], g_A1l[512 * 2048];
__device__ __nv_bfloat16 g_A2h[128 * 512],  g_A2l[128 * 512];
__device__ __nv_bfloat16 g_A3h[128 * 128],  g_A3l[128 * 128];  // M padded 64->128
__device__ __nv_bfloat16 g_Bh[2 * 2048 * 3200], g_Bl[2 * 2048 * 3200];

// combine weights W^T, bf16 hi/lo, chunk layout [kc][m][64]
__device__ __nv_bfloat16 g_Wt1h[32 * 64],  g_Wt1l[32 * 64];
__device__ __nv_bfloat16 g_Wt2h[2 * 64 * 64], g_Wt2l[2 * 64 * 64];

__device__ int g_off0[2049], g_perm0[16384];
__device__ int g_off1[513],  g_perm1[8192];
__device__ int g_off2[129],  g_perm2[2048];
__device__ float g_inv0[2048], g_inv1[512], g_inv2[128];

// ---------------------------- helpers ---------------------------------------
__device__ __forceinline__ uint32_t smem_u32(const void* p) {
    uint32_t a;
    asm("{ .reg .u64 t; cvta.to.shared.u64 t, %1; cvt.u32.u64 %0, t; }"
        : "=r"(a) : "l"(p));
    return a;
}

#define SW128(x) ((x) ^ (((x) >> 3) & 0x70))

#define LDM4(r, addr)                                                            \
    asm volatile("ldmatrix.sync.aligned.m8n8.x4.shared.b16 {%0,%1,%2,%3}, [%4];" \
                 : "=r"((r)[0]), "=r"((r)[1]), "=r"((r)[2]), "=r"((r)[3])        \
                 : "r"(addr))

#define LDM2T(r, addr)                                                           \
    asm volatile("ldmatrix.sync.aligned.m8n8.x2.trans.shared.b16 {%0,%1}, [%2];" \
                 : "=r"((r)[0]), "=r"((r)[1]) : "r"(addr))

#define MMA_BF16(c, a, bb)                                                       \
    asm volatile("mma.sync.aligned.m16n8k16.row.col.f32.bf16.bf16.f32 "          \
                 "{%0,%1,%2,%3}, {%4,%5,%6,%7}, {%8,%9}, {%0,%1,%2,%3};"         \
                 : "+f"((c)[0]), "+f"((c)[1]), "+f"((c)[2]), "+f"((c)[3])        \
                 : "r"((a)[0]), "r"((a)[1]), "r"((a)[2]), "r"((a)[3]),           \
                   "r"((bb)[0]), "r"((bb)[1]))

#define CP16(dst, src)                                                           \
    asm volatile("cp.async.cg.shared.global [%0], [%1], 16;" :: "r"(dst), "l"(src))
#define CP_COMMIT asm volatile("cp.async.commit_group;" ::: "memory")
#define CP_WAIT0  asm volatile("cp.async.wait_group 0;" ::: "memory")

__device__ __forceinline__ uint32_t pack_bf2(float a, float b) {
    __nv_bfloat16 ha = __float2bfloat16(a), hb = __float2bfloat16(b);
    return (uint32_t)__bfloat16_as_ushort(ha) |
           ((uint32_t)__bfloat16_as_ushort(hb) << 16);
}

// -------------- merged setup: 3 CSR blocks + split/Wt blocks ----------------
__global__ __launch_bounds__(1024)
void setup_kernel(const int* e0, const int* e1, const int* e2,
                  int* o0, int* p0, float* v0,
                  int* o1, int* p1, float* v1,
                  int* o2, int* p2, float* v2,
                  const float* __restrict__ P01, const float* __restrict__ P12,
                  const float* __restrict__ P23,
                  __nv_bfloat16* A1h, __nv_bfloat16* A1l,
                  __nv_bfloat16* A2h, __nv_bfloat16* A2l,
                  __nv_bfloat16* A3h, __nv_bfloat16* A3l,
                  const float* __restrict__ Wk2, const float* __restrict__ Wr2,
                  const float* __restrict__ Wk3, const float* __restrict__ Wr3,
                  __nv_bfloat16* Wt1h, __nv_bfloat16* Wt1l,
                  __nv_bfloat16* Wt2h, __nv_bfloat16* Wt2l) {
    int tid = threadIdx.x;
    if (blockIdx.x >= 3) {
        const long S1 = 512 * 2048, S2 = 128 * 512, S3 = 128 * 128;
        const long W1 = 32 * 64, W2 = 2 * 64 * 64;
        long i = (long)(blockIdx.x - 3) * 1024 + tid;
        float v; __nv_bfloat16 *H, *L; long o;
        if (i < S1) { o = i; v = P01[o]; H = A1h; L = A1l; }
        else if (i < S1 + S2) { o = i - S1; v = P12[o]; H = A2h; L = A2l; }
        else if (i < S1 + S2 + S3) {
            o = i - S1 - S2;
            v = ((o >> 7) < 64) ? P23[o] : 0.0f;
            H = A3h; L = A3l;
        } else if (i < S1 + S2 + S3 + W1) {
            o = i - S1 - S2 - S3;
            int m = (int)(o >> 6), kk = (int)(o & 63);
            v = (kk < 48) ? Wk2[kk * 32 + m] : Wr2[(kk - 48) * 32 + m];
            H = Wt1h; L = Wt1l;
        } else if (i < S1 + S2 + S3 + W1 + W2) {
            o = i - S1 - S2 - S3 - W1;
            int kc = (int)(o >> 12), rem = (int)(o & 4095);
            int m = rem >> 6, kk = rem & 63;
            int j = kc * 64 + kk;
            v = (j < 96) ? Wk3[j * 64 + m] : Wr3[(j - 96) * 64 + m];
            H = Wt2h; L = Wt2l;
        } else return;
        __nv_bfloat16 hi = __float2bfloat16(v);
        H[o] = hi;
        L[o] = __float2bfloat16(v - __bfloat162float(hi));
        return;
    }
    // ---- CSR part: one block per level ----
    __shared__ int sa[2048];
    __shared__ int sb[2048];
    __shared__ int scur[2048];
    int lvl = blockIdx.x;
    const int* dst = lvl == 0 ? e0 + 16384 : (lvl == 1 ? e1 + 8192 : e2 + 2048);
    int E = lvl == 0 ? 16384 : (lvl == 1 ? 8192 : 2048);
    int N = lvl == 0 ? 2048 : (lvl == 1 ? 512 : 128);
    int* off = lvl == 0 ? o0 : (lvl == 1 ? o1 : o2);
    int* perm = lvl == 0 ? p0 : (lvl == 1 ? p1 : p2);
    float* inv = lvl == 0 ? v0 : (lvl == 1 ? v1 : v2);

    for (int q = tid; q < 2048; q += 1024) sa[q] = 0;
    __syncthreads();
    for (int i = tid; i < E; i += 1024) atomicAdd(&sa[dst[i]], 1);
    __syncthreads();
    for (int q = tid; q < 2048; q += 1024) {
        int dg = sa[q];
        sb[q] = dg;
        if (q < N) inv[q] = 1.0f / (float)(dg > 0 ? dg : 1);
    }
    __syncthreads();
    int* pc = sa;
    int* pn = scur;
    for (int d = 1; d < 2048; d <<= 1) {
        for (int q = tid; q < 2048; q += 1024) {
            int v = pc[q];
            if (q >= d) v += pc[q - d];
            pn[q] = v;
        }
        __syncthreads();
        int* t = pc; pc = pn; pn = t;
    }
    for (int q = tid; q < N; q += 1024) {
        int o = (q == 0) ? 0 : pc[q - 1];
        off[q] = o;
        pn[q] = o;
    }
    if (tid == 0) off[N] = pc[N - 1];
    __syncthreads();
    for (int i = tid; i < E; i += 1024) {
        int p = atomicAdd(&pn[dst[i]], 1);
        perm[p] = i;
    }
    __syncthreads();
    for (int n = tid; n < N; n += 1024) {
        int a = (n == 0) ? 0 : pc[n - 1];
        int b = pc[n];
        for (int k = a + 1; k < b; k++) {
            int v = perm[k];
            int j = k - 1;
            while (j >= a && perm[j] > v) { perm[j + 1] = perm[j]; j--; }
            perm[j + 1] = v;
        }
    }
}

// ------- level-1 GCN (both batches per block, staged edge weights) ----------
__global__ __launch_bounds__(256)
void gcn1_kernel(const float* __restrict__ x, const float* __restrict__ ea,
                 const float* __restrict__ Amat,
                 const float* __restrict__ Wk, const float* __restrict__ Wr,
                 const float* __restrict__ bias,
                 const int* __restrict__ srcArr, const int* __restrict__ off,
                 const int* __restrict__ perm, const float* __restrict__ inv_cnt,
                 __nv_bfloat16* __restrict__ Bh, __nv_bfloat16* __restrict__ Bl) {
    __shared__ float sA[9];
    __shared__ float sW[80];
    __shared__ int sSrc[64];
    __shared__ float sEw[64 * 3];
    const int N0 = 2048;
    int n = blockIdx.x;
    int t = threadIdx.x;
    if (t < 9) sA[t] = Amat[t];
    if (t < 48) sW[t] = Wk[t];
    else if (t < 64) sW[t] = Wr[t - 48];
    else if (t < 80) sW[t] = bias[t - 64];
    __syncthreads();

    float a0[3] = {0.f, 0.f, 0.f};
    float a1[3] = {0.f, 0.f, 0.f};
    int e0 = off[n], e1 = off[n + 1];
    for (int base = e0; base < e1; base += 64) {
        int cnt = min(64, e1 - base);
        __syncthreads();
        if (t < cnt) {
            int e = perm[base + t];
            sSrc[t] = srcArr[e];
            float u0 = ea[e * 3 + 0], u1 = ea[e * 3 + 1], u2 = ea[e * 3 + 2];
            float w0 = u0 * sA[0] + u1 * sA[3] + u2 * sA[6];
            float w1 = u0 * sA[1] + u1 * sA[4] + u2 * sA[7];
            float w2 = u0 * sA[2] + u1 * sA[5] + u2 * sA[8];
            float m = fmaxf(w0, fmaxf(w1, w2));
            float q0 = __expf(w0 - m), q1 = __expf(w1 - m), q2 = __expf(w2 - m);
            float qi = 1.0f / (q0 + q1 + q2);
            sEw[t * 3 + 0] = q0 * qi;
            sEw[t * 3 + 1] = q1 * qi;
            sEw[t * 3 + 2] = q2 * qi;
        }
        __syncthreads();
        if (t < TT) {
#pragma unroll 2
            for (int j = 0; j < cnt; j++) {
                int src = sSrc[j];
                float w0 = sEw[j * 3 + 0], w1 = sEw[j * 3 + 1], w2 = sEw[j * 3 + 2];
                float va = x[src * TT + t];
                float vb = x[(N0 + src) * TT + t];
                a0[0] += w0 * va; a0[1] += w1 * va; a0[2] += w2 * va;
                a1[0] += w0 * vb; a1[1] += w1 * vb; a1[2] += w2 * vb;
            }
        }
    }
    if (t >= TT) return;
    float inv = inv_cnt[n];
#pragma unroll
    for (int k = 0; k < 3; k++) { a0[k] *= inv; a1[k] *= inv; }
    float xo0 = x[n * TT + t];
    float xo1 = x[(N0 + n) * TT + t];
    long base0 = ((long)n * 16) * TT + t;
    long base1 = ((long)(N0 + n) * 16) * TT + t;
#pragma unroll
    for (int o = 0; o < 16; o++) {
        float v = a0[0] * sW[o] + a0[1] * sW[16 + o] + a0[2] * sW[32 + o] +
                  xo0 * sW[48 + o] + sW[64 + o];
        v = v > 0.0f ? v : expm1f(v);
        __nv_bfloat16 hi = __float2bfloat16(v);
        Bh[base0 + (long)o * TT] = hi;
        Bl[base0 + (long)o * TT] = __float2bfloat16(v - __bfloat162float(hi));
        v = a1[0] * sW[o] + a1[1] * sW[16 + o] + a1[2] * sW[32 + o] +
            xo1 * sW[48 + o] + sW[64 + o];
        v = v > 0.0f ? v : expm1f(v);
        hi = __float2bfloat16(v);
        Bh[base1 + (long)o * TT] = hi;
        Bl[base1 + (long)o * TT] = __float2bfloat16(v - __bfloat162float(hi));
    }
}

// ----- fused GCN level: scalar gather + tensor-core combine -----------------
// Wt is staged in smem only transiently; its region is aliased by cat.
// dyn smem: [0, K4*400) chi | [K4*400, 2*K4*400) clo | sbias
template <int CIN, int COUT>
__global__ __launch_bounds__(256)
void gcnf_kernel(const float* __restrict__ xin, const float* __restrict__ ea,
                 const float* __restrict__ Amat,
                 const __nv_bfloat16* __restrict__ Wth,
                 const __nv_bfloat16* __restrict__ Wtl,
                 const float* __restrict__ bias,
                 const int* __restrict__ srcArr, const int* __restrict__ off,
                 const int* __restrict__ perm, const float* __restrict__ inv_cnt,
                 __nv_bfloat16* __restrict__ Bh, __nv_bfloat16* __restrict__ Bl, int Nn) {
    constexpr int K4 = 4 * CIN;
    constexpr int KCH = K4 / 64;
    constexpr int MT = COUT / 16;
    constexpr int KQ = K4 / 16;
    constexpr uint32_t WSZ = KCH * COUT * 128;  // one Wt operand staging size
    extern __shared__ __align__(16) char dsm[];
    const uint32_t chi_o = 0;
    const uint32_t clo_o = K4 * 400;
    float* sbias = (float*)(dsm + 2 * K4 * 400);
    uint32_t sb = smem_u32(dsm);
    __shared__ float sA[9];
    __shared__ int sSrc[64];
    __shared__ float sEw[64 * 3];

    int n = blockIdx.x, b = blockIdx.y;
    int tid = threadIdx.x, lane = tid & 31, w = tid >> 5;
    int tx = lane, ty = w;
    if (tid < 9) sA[tid] = Amat[tid];
    if (tid < COUT) sbias[tid] = bias[tid];
    // transiently stage W^T at offsets 0 / WSZ (will be overwritten by cat)
    {
        const uint4* WhG = (const uint4*)Wth;
        const uint4* WlG = (const uint4*)Wtl;
        for (int q = tid; q < KCH * COUT * 8; q += 256) {
            int kc = q / (COUT * 8);
            int rem = q - kc * (COUT * 8);
            int m = rem >> 3, seg = rem & 7;
            uint32_t d = kc * COUT * 128 + SW128(m * 128 + seg * 16);
            *(uint4*)(dsm + d) = WhG[q];
            *(uint4*)(dsm + WSZ + d) = WlG[q];
        }
    }
    __syncthreads();

    // ---- load combine A-fragments into registers (frees Wt smem) ----
    int mt = w % MT;
    uint32_t ah[KQ][4], al[KQ][4];
#pragma unroll
    for (int kq = 0; kq < KQ; kq++) {
        int kc = kq >> 2, ks = kq & 3;
        uint32_t offA = kc * COUT * 128 +
                        SW128((mt * 16 + (lane & 15)) * 128 + ks * 32 + (lane >> 4) * 16);
        LDM4(ah[kq], sb + offA);
        LDM4(al[kq], sb + WSZ + offA);
    }
    __syncthreads();  // Wt reads complete before cat overwrites (deg-0 safety)

    // ---- gather (scalar form): acc[k][u][s], (ch = ty+8u, t = tx+32s) ----
    constexpr int U = CIN / 8;
    float acc[3][U][7];
#pragma unroll
    for (int k = 0; k < 3; k++)
#pragma unroll
        for (int u = 0; u < U; u++)
#pragma unroll
            for (int s = 0; s < 7; s++) acc[k][u][s] = 0.0f;

    int e0 = off[n], e1 = off[n + 1];
    for (int base = e0; base < e1; base += 64) {
        int cnt = min(64, e1 - base);
        __syncthreads();
        if (tid < cnt) {
            int e = perm[base + tid];
            sSrc[tid] = srcArr[e];
            float u0 = ea[e * 3 + 0], u1 = ea[e * 3 + 1], u2 = ea[e * 3 + 2];
            float w0 = u0 * sA[0] + u1 * sA[3] + u2 * sA[6];
            float w1 = u0 * sA[1] + u1 * sA[4] + u2 * sA[7];
            float w2 = u0 * sA[2] + u1 * sA[5] + u2 * sA[8];
            float m = fmaxf(w0, fmaxf(w1, w2));
            float q0 = __expf(w0 - m), q1 = __expf(w1 - m), q2 = __expf(w2 - m);
            float qi = 1.0f / (q0 + q1 + q2);
            sEw[tid * 3 + 0] = q0 * qi;
            sEw[tid * 3 + 1] = q1 * qi;
            sEw[tid * 3 + 2] = q2 * qi;
        }
        __syncthreads();
        for (int j = 0; j < cnt; j++) {
            float q0 = sEw[j * 3 + 0], q1 = sEw[j * 3 + 1], q2 = sEw[j * 3 + 2];
            const float* xp = xin + (long)(b * Nn + sSrc[j]) * (CIN * TT);
#pragma unroll
            for (int u = 0; u < U; u++) {
#pragma unroll
                for (int s = 0; s < 7; s++) {
                    int t = tx + 32 * s;
                    float v = xp[(ty + 8 * u) * TT + (t < TT ? t : 0)];
                    acc[0][u][s] += q0 * v;
                    acc[1][u][s] += q1 * v;
                    acc[2][u][s] += q2 * v;
                }
            }
        }
    }

    // ---- build cat = [G | x] in bf16 hi/lo smem (overwrites Wt region) ----
    float inv = inv_cnt[n];
    __syncthreads();
    __nv_bfloat16* chi = (__nv_bfloat16*)(dsm + chi_o);
    __nv_bfloat16* clo = (__nv_bfloat16*)(dsm + clo_o);
#pragma unroll
    for (int k = 0; k < 3; k++)
#pragma unroll
        for (int u = 0; u < U; u++)
#pragma unroll
            for (int s = 0; s < 7; s++) {
                int t = tx + 32 * s;
                if (t < TT) {
                    int row = k * CIN + ty + 8 * u;
                    float v = acc[k][u][s] * inv;
                    __nv_bfloat16 hi = __float2bfloat16(v);
                    chi[row * TT + t] = hi;
                    clo[row * TT + t] = __float2bfloat16(v - __bfloat162float(hi));
                }
            }
    {
        const float* xp = xin + (long)(b * Nn + n) * (CIN * TT);
#pragma unroll
        for (int u = 0; u < U; u++)
#pragma unroll
            for (int s = 0; s < 7; s++) {
                int t = tx + 32 * s;
                if (t < TT) {
                    int c = ty + 8 * u;
                    float v = xp[c * TT + t];
                    int row = 3 * CIN + c;
                    __nv_bfloat16 hi = __float2bfloat16(v);
                    chi[row * TT + t] = hi;
                    clo[row * TT + t] = __float2bfloat16(v - __bfloat162float(hi));
                }
            }
    }
    __syncthreads();

    // ---- combine on tensor cores: out[COUT x 200] = Wt @ cat, bf16x3 ----
    int ntStart = w / MT;
    constexpr int NTSTRIDE = 8 / MT;

    long obase = (long)(b * Nn + n) * (COUT * TT);
    int o0 = mt * 16 + (lane >> 2);
    float bb0 = sbias[o0], bb1 = sbias[o0 + 8];
    for (int nt = ntStart; nt < 25; nt += NTSTRIDE) {
        float c[4] = {0.f, 0.f, 0.f, 0.f};
#pragma unroll
        for (int kq = 0; kq < KQ; kq++) {
            uint32_t offB = (uint32_t)(kq * 16 + (lane & 15)) * 400 + nt * 16;
            uint32_t bh[2], bl[2];
            LDM2T(bh, sb + chi_o + offB);
            LDM2T(bl, sb + clo_o + offB);
            MMA_BF16(c, ah[kq], bh);
            MMA_BF16(c, ah[kq], bl);
            MMA_BF16(c, al[kq], bh);
        }
        int t0 = nt * 8 + (lane & 3) * 2;
        float v0 = c[0] + bb0; v0 = v0 > 0.f ? v0 : expm1f(v0);
        float v1 = c[1] + bb0; v1 = v1 > 0.f ? v1 : expm1f(v1);
        __nv_bfloat16 h0 = __float2bfloat16(v0), h1 = __float2bfloat16(v1);
        *(uint32_t*)&Bh[obase + (long)o0 * TT + t0] =
            (uint32_t)__bfloat16_as_ushort(h0) | ((uint32_t)__bfloat16_as_ushort(h1) << 16);
        *(uint32_t*)&Bl[obase + (long)o0 * TT + t0] =
            pack_bf2(v0 - __bfloat162float(h0), v1 - __bfloat162float(h1));
        float v2 = c[2] + bb1; v2 = v2 > 0.f ? v2 : expm1f(v2);
        float v3 = c[3] + bb1; v3 = v3 > 0.f ? v3 : expm1f(v3);
        __nv_bfloat16 h2 = __float2bfloat16(v2), h3 = __float2bfloat16(v3);
        *(uint32_t*)&Bh[obase + (long)(o0 + 8) * TT + t0] =
            (uint32_t)__bfloat16_as_ushort(h2) | ((uint32_t)__bfloat16_as_ushort(h3) << 16);
        *(uint32_t*)&Bl[obase + (long)(o0 + 8) * TT + t0] =
            pack_bf2(v2 - __bfloat162float(h2), v3 - __bfloat162float(h3));
    }
}

// ------- bf16x3 GEMM (R8): Kc=64, 96KB, cp.async double-buffered -------------
__global__ __launch_bounds__(256)
void mma_gemm_kernel(const __nv_bfloat16* __restrict__ Ahi, const __nv_bfloat16* __restrict__ Alo,
                     const __nv_bfloat16* __restrict__ Bhi, const __nv_bfloat16* __restrict__ Blo,
                     float* __restrict__ C, int Mout, int K, int F) {
    extern __shared__ __align__(16) char smem[];
    const int BUF = 49152;
    const int OFF_AH = 0, OFF_AL = 16384, OFF_BH = 32768, OFF_BL = 40960;
    uint32_t sbase = smem_u32(smem);
    int tid = threadIdx.x, lane = tid & 31, w = tid >> 5;
    int mw = w & 1, fw = w >> 1;
    int f0 = blockIdx.x * 64, row0 = blockIdx.y * 128, b = blockIdx.z;

    const __nv_bfloat16* BhB = Bhi + (long)b * K * F;
    const __nv_bfloat16* BlB = Blo + (long)b * K * F;

    float acc[4][2][4];
#pragma unroll
    for (int mt = 0; mt < 4; mt++)
#pragma unroll
        for (int nt = 0; nt < 2; nt++)
#pragma unroll
            for (int q = 0; q < 4; q++) acc[mt][nt][q] = 0.0f;

    int r = tid >> 3, cb = (tid & 7) * 16;
    int nchunk = K >> 6;

#define STAGE(bo, k0)                                                              \
    do {                                                                           \
        _Pragma("unroll")                                                          \
        for (int i = 0; i < 4; i++) {                                              \
            int rr = r + i * 32;                                                   \
            uint32_t so = SW128(rr * 128 + cb);                                    \
            CP16(sbase + (bo) + OFF_AH + so,                                       \
                 (const char*)&Ahi[(long)(row0 + rr) * K + (k0) + (cb >> 1)]);     \
            CP16(sbase + (bo) + OFF_AL + so,                                       \
                 (const char*)&Alo[(long)(row0 + rr) * K + (k0) + (cb >> 1)]);     \
        }                                                                          \
        _Pragma("unroll")                                                          \
        for (int i = 0; i < 2; i++) {                                              \
            int rr = r + i * 32;                                                   \
            uint32_t so = SW128(rr * 128 + cb);                                    \
            long gi = (long)((k0) + rr) * F + f0 + (cb >> 1);                      \
            CP16(sbase + (bo) + OFF_BH + so, (const char*)&BhB[gi]);               \
            CP16(sbase + (bo) + OFF_BL + so, (const char*)&BlB[gi]);               \
        }                                                                          \
    } while (0)

    STAGE(0, 0);
    CP_COMMIT;

    int buf = 0;
    for (int kc = 0; kc < nchunk; kc++) {
        CP_WAIT0;
        __syncthreads();
        if (kc + 1 < nchunk) {
            STAGE((buf ^ 1) * BUF, (kc + 1) << 6);
            CP_COMMIT;
        }
        int bo = buf * BUF;
#pragma unroll
        for (int ks = 0; ks < 4; ks++) {
            uint32_t ah[4][4], al[4][4], bh[2][2], bl[2][2];
#pragma unroll
            for (int mt = 0; mt < 4; mt++) {
                uint32_t off = SW128((mw * 64 + mt * 16 + (lane & 15)) * 128 +
                                     ks * 32 + (lane >> 4) * 16);
                LDM4(ah[mt], sbase + bo + OFF_AH + off);
                LDM4(al[mt], sbase + bo + OFF_AL + off);
            }
#pragma unroll
            for (int nt = 0; nt < 2; nt++) {
                uint32_t off = SW128((ks * 16 + (lane & 15)) * 128 + fw * 32 + nt * 16);
                LDM2T(bh[nt], sbase + bo + OFF_BH + off);
                LDM2T(bl[nt], sbase + bo + OFF_BL + off);
            }
#pragma unroll
            for (int mt = 0; mt < 4; mt++) {
#pragma unroll
                for (int nt = 0; nt < 2; nt++) {
                    MMA_BF16(acc[mt][nt], ah[mt], bh[nt]);
                    MMA_BF16(acc[mt][nt], ah[mt], bl[nt]);
                    MMA_BF16(acc[mt][nt], al[mt], bh[nt]);
                }
            }
        }
        __syncthreads();
        buf ^= 1;
    }
#undef STAGE

#pragma unroll
    for (int mt = 0; mt < 4; mt++) {
        int gr = row0 + mw * 64 + mt * 16 + (lane >> 2);
#pragma unroll
        for (int nt = 0; nt < 2; nt++) {
            int gc = f0 + fw * 16 + nt * 8 + (lane & 3) * 2;
            if (gr < Mout)
                *(float2*)&C[((long)b * Mout + gr) * F + gc] =
                    make_float2(acc[mt][nt][0], acc[mt][nt][1]);
            if (gr + 8 < Mout)
                *(float2*)&C[((long)b * Mout + gr + 8) * F + gc] =
                    make_float2(acc[mt][nt][2], acc[mt][nt][3]);
        }
    }
}

// ------------ fused head: elu(p3@W1+b1) -> tanh(.@W2+b2), smem hm -----------
__global__ __launch_bounds__(256)
void head_kernel(const float* __restrict__ p3,
                 const float* __restrict__ f1w, const float* __restrict__ f1b,
                 const float* __restrict__ f2w, const float* __restrict__ f2b,
                 float* __restrict__ out, int Nn) {
    extern __shared__ __align__(16) float ds[];
    float* w1 = ds;
    float* w2 = w1 + 8192;
    float* b1s = w2 + 8192;
    float* b2s = b1s + 128;
    float* hmS = b2s + 64;
    int n = blockIdx.x, b = blockIdx.y;
    int tid = threadIdx.x, tx = tid & 31, ty = tid >> 5;
    for (int q = tid; q < 8192; q += 256) { w1[q] = f1w[q]; w2[q] = f2w[q]; }
    if (tid < 128) b1s[tid] = f1b[tid];
    if (tid < 64) b2s[tid] = f2b[tid];
    __syncthreads();

    const float* xp = p3 + (long)(b * Nn + n) * (64 * TT);
    float* op = out + (long)(b * Nn + n) * (64 * TT);

    for (int tz = 0; tz < 2; tz++) {
        int toff = tz * 100;
        float acc1[16][4];
#pragma unroll
        for (int u = 0; u < 16; u++)
#pragma unroll
            for (int s = 0; s < 4; s++) acc1[u][s] = 0.0f;
#pragma unroll 4
        for (int j = 0; j < 64; j++) {
            float xr[4];
#pragma unroll
            for (int s = 0; s < 4; s++) {
                int t = tx + 32 * s;
                xr[s] = xp[j * TT + toff + (t < 100 ? t : 0)];
            }
#pragma unroll
            for (int u = 0; u < 16; u++) {
                float w = w1[j * 128 + ty + 8 * u];
#pragma unroll
                for (int s = 0; s < 4; s++) acc1[u][s] += w * xr[s];
            }
        }
        __syncthreads();
#pragma unroll
        for (int u = 0; u < 16; u++) {
            int o = ty + 8 * u;
            float bb = b1s[o];
#pragma unroll
            for (int s = 0; s < 4; s++) {
                int t = tx + 32 * s;
                if (t < 100) {
                    float v = acc1[u][s] + bb;
                    v = v > 0.0f ? v : expm1f(v);
                    hmS[o * 100 + t] = v;
                }
            }
        }
        __syncthreads();
        float acc2[8][4];
#pragma unroll
        for (int u = 0; u < 8; u++)
#pragma unroll
            for (int s = 0; s < 4; s++) acc2[u][s] = 0.0f;
#pragma unroll 4
        for (int j = 0; j < 128; j++) {
            float xr[4];
#pragma unroll
            for (int s = 0; s < 4; s++) {
                int t = tx + 32 * s;
                xr[s] = hmS[j * 100 + (t < 100 ? t : 0)];
            }
#pragma unroll
            for (int u = 0; u < 8; u++) {
                float w = w2[j * 64 + ty + 8 * u];
#pragma unroll
                for (int s = 0; s < 4; s++) acc2[u][s] += w * xr[s];
            }
        }
#pragma unroll
        for (int u = 0; u < 8; u++) {
            int o = ty + 8 * u;
            float bb = b2s[o];
#pragma unroll
            for (int s = 0; s < 4; s++) {
                int t = tx + 32 * s;
                if (t < 100) op[o * TT + toff + t] = tanhf(acc2[u][s] + bb);
            }
        }
        __syncthreads();
    }
}

// -------------------------------- launch ------------------------------------
#define GETSYM(var, sym)                                       \
    do {                                                       \
        void* _p = nullptr;                                    \
        cudaGetSymbolAddress(&_p, sym);                        \
        var = (decltype(var))_p;                               \
    } while (0)

extern "C" void kernel_launch(void* const* d_in, const int* in_sizes, int n_in,
                              void* d_out, int out_size) {
    (void)in_sizes; (void)n_in; (void)out_size;
    const float* x   = (const float*)d_in[0];
    const int*   ei0 = (const int*)d_in[1];
    const float* ea0 = (const float*)d_in[2];
    const int*   ei1 = (const int*)d_in[3];
    const float* ea1 = (const float*)d_in[4];
    const int*   ei2 = (const int*)d_in[5];
    const float* ea2 = (const float*)d_in[6];
    const float* A1  = (const float*)d_in[7];
    const float* Wk1 = (const float*)d_in[8];
    const float* Wr1 = (const float*)d_in[9];
    const float* b1  = (const float*)d_in[10];
    const float* A2  = (const float*)d_in[11];
    const float* Wk2 = (const float*)d_in[12];
    const float* Wr2 = (const float*)d_in[13];
    const float* b2  = (const float*)d_in[14];
    const float* A3  = (const float*)d_in[15];
    const float* Wk3 = (const float*)d_in[16];
    const float* Wr3 = (const float*)d_in[17];
    const float* b3  = (const float*)d_in[18];
    const float* P01 = (const float*)d_in[19];
    const float* P12 = (const float*)d_in[20];
    const float* P23 = (const float*)d_in[21];
    const float* f1w = (const float*)d_in[22];
    const float* f1b = (const float*)d_in[23];
    const float* f2w = (const float*)d_in[24];
    const float* f2b = (const float*)d_in[25];

    const int N0 = 2048, N1 = 512, N2 = 128, N3 = 64;

    float *p1, *p2, *p3;
    __nv_bfloat16 *A1h, *A1l, *A2h, *A2l, *A3h, *A3l, *Bh, *Bl;
    __nv_bfloat16 *Wt1h, *Wt1l, *Wt2h, *Wt2l;
    int *off0, *perm0, *off1, *perm1, *off2, *perm2;
    float *inv0, *inv1, *inv2;
    GETSYM(p1, g_p1); GETSYM(p2, g_p2); GETSYM(p3, g_p3);
    GETSYM(A1h, g_A1h); GETSYM(A1l, g_A1l);
    GETSYM(A2h, g_A2h); GETSYM(A2l, g_A2l);
    GETSYM(A3h, g_A3h); GETSYM(A3l, g_A3l);
    GETSYM(Bh, g_Bh); GETSYM(Bl, g_Bl);
    GETSYM(Wt1h, g_Wt1h); GETSYM(Wt1l, g_Wt1l);
    GETSYM(Wt2h, g_Wt2h); GETSYM(Wt2l, g_Wt2l);
    GETSYM(off0, g_off0); GETSYM(perm0, g_perm0);
    GETSYM(off1, g_off1); GETSYM(perm1, g_perm1);
    GETSYM(off2, g_off2); GETSYM(perm2, g_perm2);
    GETSYM(inv0, g_inv0); GETSYM(inv1, g_inv1); GETSYM(inv2, g_inv2);

    const int SMEM_GEMM = 98304;
    cudaFuncSetAttribute(mma_gemm_kernel, cudaFuncAttributeMaxDynamicSharedMemorySize,
                         SMEM_GEMM);
    // cat-only dynamic smem (Wt region aliased): 2*K4*400 + COUT*4
    const int SMEM_F1 = 2 * 64 * 400 + 32 * 4;    // ~50.1KB -> 4 blocks/SM
    const int SMEM_F2 = 2 * 128 * 400 + 64 * 4;   // ~100.3KB -> 2 blocks/SM
    cudaFuncSetAttribute((const void*)gcnf_kernel<16, 32>,
                         cudaFuncAttributeMaxDynamicSharedMemorySize, SMEM_F1);
    cudaFuncSetAttribute((const void*)gcnf_kernel<32, 64>,
                         cudaFuncAttributeMaxDynamicSharedMemorySize, SMEM_F2);
    const int SMEM_HEAD = (8192 + 8192 + 128 + 64 + 12800) * 4;
    cudaFuncSetAttribute(head_kernel, cudaFuncAttributeMaxDynamicSharedMemorySize,
                         SMEM_HEAD);

    // ---- setup: CSR (3 blocks) + splitA + Wt, one launch ----
    const long SPLIT_TOT = 512L * 2048 + 128 * 512 + 128 * 128 + 32 * 64 + 2 * 64 * 64;
    setup_kernel<<<3 + (int)((SPLIT_TOT + 1023) / 1024), 1024>>>(
        ei0, ei1, ei2, off0, perm0, inv0, off1, perm1, inv1, off2, perm2, inv2,
        P01, P12, P23, A1h, A1l, A2h, A2l, A3h, A3l,
        Wk2, Wr2, Wk3, Wr3, Wt1h, Wt1l, Wt2h, Wt2l);

    // ---- level 0->1 GCN ----
    gcn1_kernel<<<N0, 256>>>(x, ea0, A1, Wk1, Wr1, b1, ei0, off0, perm0, inv0, Bh, Bl);

    // ---- pool1: M=512, K=2048, F=3200 ----
    mma_gemm_kernel<<<dim3(3200 / 64, 512 / 128, 2), 256, SMEM_GEMM>>>(
        A1h, A1l, Bh, Bl, p1, 512, 2048, 3200);

    // ---- level 1->2 GCN (scalar gather + tensor-core combine) ----
    gcnf_kernel<16, 32><<<dim3(N1, 2), 256, SMEM_F1>>>(
        p1, ea1, A2, Wt1h, Wt1l, b2, ei1, off1, perm1, inv1, Bh, Bl, N1);

    // ---- pool2: M=128, K=512, F=6400 ----
    mma_gemm_kernel<<<dim3(6400 / 64, 1, 2), 256, SMEM_GEMM>>>(
        A2h, A2l, Bh, Bl, p2, 128, 512, 6400);

    // ---- level 2->3 GCN ----
    gcnf_kernel<32, 64><<<dim3(N2, 2), 256, SMEM_F2>>>(
        p2, ea2, A3, Wt2h, Wt2l, b3, ei2, off2, perm2, inv2, Bh, Bl, N2);

    // ---- pool3: M=64 (padded 128), K=128, F=12800 ----
    mma_gemm_kernel<<<dim3(12800 / 64, 1, 2), 256, SMEM_GEMM>>>(
        A3h, A3l, Bh, Bl, p3, 64, 128, 12800);

    // ---- fused head ----
    head_kernel<<<dim3(N3, 2), 256, SMEM_HEAD>>>(
        p3, f1w, f1b, f2w, f2b, (float*)d_out, N3);
}

// round 14
// speedup vs baseline: 1.2499x; 1.2499x over previous
#include <cuda_runtime.h>
#include <cuda_bf16.h>
#include <cstdint>

// ============================================================================
// Graph_ODE_RNN — 8-launch pipeline (best-known config = R8):
//  [csr+splitA+Wt] -> gcn1 -> pool1 -> gcnf1 -> pool2 -> gcnf2 -> pool3 -> head
//  gcnf: scalar gather + tensor-core combine, Wt in own smem, frags post-gather
//  pool GEMM: bf16x3 mma.sync, Kc=64, 96KB cp.async double buffer
// ============================================================================

#define TT 200

// ---------------- static scratch (no allocation allowed) -------------------
__device__ float g_p1[2 * 512 * 16 * TT];
__device__ float g_p2[2 * 128 * 32 * TT];
__device__ float g_p3[2 * 64 * 64 * TT];

__device__ __nv_bfloat16 g_A1h[512 * 2048], g_A1l[512 * 2048];
__device__ __nv_bfloat16 g_A2h[128 * 512],  g_A2l[128 * 512];
__device__ __nv_bfloat16 g_A3h[128 * 128],  g_A3l[128 * 128];  // M padded 64->128
__device__ __nv_bfloat16 g_Bh[2 * 2048 * 3200], g_Bl[2 * 2048 * 3200];

// combine weights W^T, bf16 hi/lo, chunk layout [kc][m][64]
__device__ __nv_bfloat16 g_Wt1h[32 * 64],  g_Wt1l[32 * 64];
__device__ __nv_bfloat16 g_Wt2h[2 * 64 * 64], g_Wt2l[2 * 64 * 64];

__device__ int g_off0[2049], g_perm0[16384];
__device__ int g_off1[513],  g_perm1[8192];
__device__ int g_off2[129],  g_perm2[2048];
__device__ float g_inv0[2048], g_inv1[512], g_inv2[128];

// ---------------------------- helpers ---------------------------------------
__device__ __forceinline__ uint32_t smem_u32(const void* p) {
    uint32_t a;
    asm("{ .reg .u64 t; cvta.to.shared.u64 t, %1; cvt.u32.u64 %0, t; }"
        : "=r"(a) : "l"(p));
    return a;
}

#define SW128(x) ((x) ^ (((x) >> 3) & 0x70))

#define LDM4(r, addr)                                                            \
    asm volatile("ldmatrix.sync.aligned.m8n8.x4.shared.b16 {%0,%1,%2,%3}, [%4];" \
                 : "=r"((r)[0]), "=r"((r)[1]), "=r"((r)[2]), "=r"((r)[3])        \
                 : "r"(addr))

#define LDM2T(r, addr)                                                           \
    asm volatile("ldmatrix.sync.aligned.m8n8.x2.trans.shared.b16 {%0,%1}, [%2];" \
                 : "=r"((r)[0]), "=r"((r)[1]) : "r"(addr))

#define MMA_BF16(c, a, bb)                                                       \
    asm volatile("mma.sync.aligned.m16n8k16.row.col.f32.bf16.bf16.f32 "          \
                 "{%0,%1,%2,%3}, {%4,%5,%6,%7}, {%8,%9}, {%0,%1,%2,%3};"         \
                 : "+f"((c)[0]), "+f"((c)[1]), "+f"((c)[2]), "+f"((c)[3])        \
                 : "r"((a)[0]), "r"((a)[1]), "r"((a)[2]), "r"((a)[3]),           \
                   "r"((bb)[0]), "r"((bb)[1]))

#define CP16(dst, src)                                                           \
    asm volatile("cp.async.cg.shared.global [%0], [%1], 16;" :: "r"(dst), "l"(src))
#define CP_COMMIT asm volatile("cp.async.commit_group;" ::: "memory")
#define CP_WAIT0  asm volatile("cp.async.wait_group 0;" ::: "memory")

__device__ __forceinline__ uint32_t pack_bf2(float a, float b) {
    __nv_bfloat16 ha = __float2bfloat16(a), hb = __float2bfloat16(b);
    return (uint32_t)__bfloat16_as_ushort(ha) |
           ((uint32_t)__bfloat16_as_ushort(hb) << 16);
}

// -------------- merged setup: 3 CSR blocks + split/Wt blocks ----------------
__global__ __launch_bounds__(1024)
void setup_kernel(const int* e0, const int* e1, const int* e2,
                  int* o0, int* p0, float* v0,
                  int* o1, int* p1, float* v1,
                  int* o2, int* p2, float* v2,
                  const float* __restrict__ P01, const float* __restrict__ P12,
                  const float* __restrict__ P23,
                  __nv_bfloat16* A1h, __nv_bfloat16* A1l,
                  __nv_bfloat16* A2h, __nv_bfloat16* A2l,
                  __nv_bfloat16* A3h, __nv_bfloat16* A3l,
                  const float* __restrict__ Wk2, const float* __restrict__ Wr2,
                  const float* __restrict__ Wk3, const float* __restrict__ Wr3,
                  __nv_bfloat16* Wt1h, __nv_bfloat16* Wt1l,
                  __nv_bfloat16* Wt2h, __nv_bfloat16* Wt2l) {
    int tid = threadIdx.x;
    if (blockIdx.x >= 3) {
        const long S1 = 512 * 2048, S2 = 128 * 512, S3 = 128 * 128;
        const long W1 = 32 * 64, W2 = 2 * 64 * 64;
        long i = (long)(blockIdx.x - 3) * 1024 + tid;
        float v; __nv_bfloat16 *H, *L; long o;
        if (i < S1) { o = i; v = P01[o]; H = A1h; L = A1l; }
        else if (i < S1 + S2) { o = i - S1; v = P12[o]; H = A2h; L = A2l; }
        else if (i < S1 + S2 + S3) {
            o = i - S1 - S2;
            v = ((o >> 7) < 64) ? P23[o] : 0.0f;
            H = A3h; L = A3l;
        } else if (i < S1 + S2 + S3 + W1) {
            o = i - S1 - S2 - S3;
            int m = (int)(o >> 6), kk = (int)(o & 63);
            v = (kk < 48) ? Wk2[kk * 32 + m] : Wr2[(kk - 48) * 32 + m];
            H = Wt1h; L = Wt1l;
        } else if (i < S1 + S2 + S3 + W1 + W2) {
            o = i - S1 - S2 - S3 - W1;
            int kc = (int)(o >> 12), rem = (int)(o & 4095);
            int m = rem >> 6, kk = rem & 63;
            int j = kc * 64 + kk;
            v = (j < 96) ? Wk3[j * 64 + m] : Wr3[(j - 96) * 64 + m];
            H = Wt2h; L = Wt2l;
        } else return;
        __nv_bfloat16 hi = __float2bfloat16(v);
        H[o] = hi;
        L[o] = __float2bfloat16(v - __bfloat162float(hi));
        return;
    }
    // ---- CSR part: one block per level ----
    __shared__ int sa[2048];
    __shared__ int sb[2048];
    __shared__ int scur[2048];
    int lvl = blockIdx.x;
    const int* dst = lvl == 0 ? e0 + 16384 : (lvl == 1 ? e1 + 8192 : e2 + 2048);
    int E = lvl == 0 ? 16384 : (lvl == 1 ? 8192 : 2048);
    int N = lvl == 0 ? 2048 : (lvl == 1 ? 512 : 128);
    int* off = lvl == 0 ? o0 : (lvl == 1 ? o1 : o2);
    int* perm = lvl == 0 ? p0 : (lvl == 1 ? p1 : p2);
    float* inv = lvl == 0 ? v0 : (lvl == 1 ? v1 : v2);

    for (int q = tid; q < 2048; q += 1024) sa[q] = 0;
    __syncthreads();
    for (int i = tid; i < E; i += 1024) atomicAdd(&sa[dst[i]], 1);
    __syncthreads();
    for (int q = tid; q < 2048; q += 1024) {
        int dg = sa[q];
        sb[q] = dg;
        if (q < N) inv[q] = 1.0f / (float)(dg > 0 ? dg : 1);
    }
    __syncthreads();
    int* pc = sa;
    int* pn = scur;
    for (int d = 1; d < 2048; d <<= 1) {
        for (int q = tid; q < 2048; q += 1024) {
            int v = pc[q];
            if (q >= d) v += pc[q - d];
            pn[q] = v;
        }
        __syncthreads();
        int* t = pc; pc = pn; pn = t;
    }
    for (int q = tid; q < N; q += 1024) {
        int o = (q == 0) ? 0 : pc[q - 1];
        off[q] = o;
        pn[q] = o;
    }
    if (tid == 0) off[N] = pc[N - 1];
    __syncthreads();
    for (int i = tid; i < E; i += 1024) {
        int p = atomicAdd(&pn[dst[i]], 1);
        perm[p] = i;
    }
    __syncthreads();
    for (int n = tid; n < N; n += 1024) {
        int a = (n == 0) ? 0 : pc[n - 1];
        int b = pc[n];
        for (int k = a + 1; k < b; k++) {
            int v = perm[k];
            int j = k - 1;
            while (j >= a && perm[j] > v) { perm[j + 1] = perm[j]; j--; }
            perm[j + 1] = v;
        }
    }
}

// ------- level-1 GCN (both batches per block, staged edge weights) ----------
__global__ __launch_bounds__(256)
void gcn1_kernel(const float* __restrict__ x, const float* __restrict__ ea,
                 const float* __restrict__ Amat,
                 const float* __restrict__ Wk, const float* __restrict__ Wr,
                 const float* __restrict__ bias,
                 const int* __restrict__ srcArr, const int* __restrict__ off,
                 const int* __restrict__ perm, const float* __restrict__ inv_cnt,
                 __nv_bfloat16* __restrict__ Bh, __nv_bfloat16* __restrict__ Bl) {
    __shared__ float sA[9];
    __shared__ float sW[80];
    __shared__ int sSrc[64];
    __shared__ float sEw[64 * 3];
    const int N0 = 2048;
    int n = blockIdx.x;
    int t = threadIdx.x;
    if (t < 9) sA[t] = Amat[t];
    if (t < 48) sW[t] = Wk[t];
    else if (t < 64) sW[t] = Wr[t - 48];
    else if (t < 80) sW[t] = bias[t - 64];
    __syncthreads();

    float a0[3] = {0.f, 0.f, 0.f};
    float a1[3] = {0.f, 0.f, 0.f};
    int e0 = off[n], e1 = off[n + 1];
    for (int base = e0; base < e1; base += 64) {
        int cnt = min(64, e1 - base);
        __syncthreads();
        if (t < cnt) {
            int e = perm[base + t];
            sSrc[t] = srcArr[e];
            float u0 = ea[e * 3 + 0], u1 = ea[e * 3 + 1], u2 = ea[e * 3 + 2];
            float w0 = u0 * sA[0] + u1 * sA[3] + u2 * sA[6];
            float w1 = u0 * sA[1] + u1 * sA[4] + u2 * sA[7];
            float w2 = u0 * sA[2] + u1 * sA[5] + u2 * sA[8];
            float m = fmaxf(w0, fmaxf(w1, w2));
            float q0 = __expf(w0 - m), q1 = __expf(w1 - m), q2 = __expf(w2 - m);
            float qi = 1.0f / (q0 + q1 + q2);
            sEw[t * 3 + 0] = q0 * qi;
            sEw[t * 3 + 1] = q1 * qi;
            sEw[t * 3 + 2] = q2 * qi;
        }
        __syncthreads();
        if (t < TT) {
#pragma unroll 2
            for (int j = 0; j < cnt; j++) {
                int src = sSrc[j];
                float w0 = sEw[j * 3 + 0], w1 = sEw[j * 3 + 1], w2 = sEw[j * 3 + 2];
                float va = x[src * TT + t];
                float vb = x[(N0 + src) * TT + t];
                a0[0] += w0 * va; a0[1] += w1 * va; a0[2] += w2 * va;
                a1[0] += w0 * vb; a1[1] += w1 * vb; a1[2] += w2 * vb;
            }
        }
    }
    if (t >= TT) return;
    float inv = inv_cnt[n];
#pragma unroll
    for (int k = 0; k < 3; k++) { a0[k] *= inv; a1[k] *= inv; }
    float xo0 = x[n * TT + t];
    float xo1 = x[(N0 + n) * TT + t];
    long base0 = ((long)n * 16) * TT + t;
    long base1 = ((long)(N0 + n) * 16) * TT + t;
#pragma unroll
    for (int o = 0; o < 16; o++) {
        float v = a0[0] * sW[o] + a0[1] * sW[16 + o] + a0[2] * sW[32 + o] +
                  xo0 * sW[48 + o] + sW[64 + o];
        v = v > 0.0f ? v : expm1f(v);
        __nv_bfloat16 hi = __float2bfloat16(v);
        Bh[base0 + (long)o * TT] = hi;
        Bl[base0 + (long)o * TT] = __float2bfloat16(v - __bfloat162float(hi));
        v = a1[0] * sW[o] + a1[1] * sW[16 + o] + a1[2] * sW[32 + o] +
            xo1 * sW[48 + o] + sW[64 + o];
        v = v > 0.0f ? v : expm1f(v);
        hi = __float2bfloat16(v);
        Bh[base1 + (long)o * TT] = hi;
        Bl[base1 + (long)o * TT] = __float2bfloat16(v - __bfloat162float(hi));
    }
}

// ----- fused GCN level: scalar gather + tensor-core combine (R8 config) -----
// dyn smem: sWh | sWl | chi | clo | sbias ; frags loaded after gather
template <int CIN, int COUT>
__global__ __launch_bounds__(256)
void gcnf_kernel(const float* __restrict__ xin, const float* __restrict__ ea,
                 const float* __restrict__ Amat,
                 const __nv_bfloat16* __restrict__ Wth,
                 const __nv_bfloat16* __restrict__ Wtl,
                 const float* __restrict__ bias,
                 const int* __restrict__ srcArr, const int* __restrict__ off,
                 const int* __restrict__ perm, const float* __restrict__ inv_cnt,
                 __nv_bfloat16* __restrict__ Bh, __nv_bfloat16* __restrict__ Bl, int Nn) {
    constexpr int K4 = 4 * CIN;
    constexpr int KCH = K4 / 64;
    constexpr int MT = COUT / 16;
    constexpr int KQ = K4 / 16;
    extern __shared__ __align__(16) char dsm[];
    const uint32_t sWh_o = 0;
    const uint32_t sWl_o = KCH * COUT * 128;
    const uint32_t chi_o = 2 * KCH * COUT * 128;
    const uint32_t clo_o = chi_o + K4 * 400;
    float* sbias = (float*)(dsm + clo_o + K4 * 400);
    uint32_t sb = smem_u32(dsm);
    __shared__ float sA[9];
    __shared__ int sSrc[64];
    __shared__ float sEw[64 * 3];

    int n = blockIdx.x, b = blockIdx.y;
    int tid = threadIdx.x, lane = tid & 31, w = tid >> 5;
    int tx = lane, ty = w;
    if (tid < 9) sA[tid] = Amat[tid];
    if (tid < COUT) sbias[tid] = bias[tid];
    {
        const uint4* WhG = (const uint4*)Wth;
        const uint4* WlG = (const uint4*)Wtl;
        for (int q = tid; q < KCH * COUT * 8; q += 256) {
            int kc = q / (COUT * 8);
            int rem = q - kc * (COUT * 8);
            int m = rem >> 3, seg = rem & 7;
            uint32_t d = kc * COUT * 128 + SW128(m * 128 + seg * 16);
            *(uint4*)(dsm + sWh_o + d) = WhG[q];
            *(uint4*)(dsm + sWl_o + d) = WlG[q];
        }
    }
    __syncthreads();

    // ---- gather (scalar form): acc[k][u][s], (ch = ty+8u, t = tx+32s) ----
    constexpr int U = CIN / 8;
    float acc[3][U][7];
#pragma unroll
    for (int k = 0; k < 3; k++)
#pragma unroll
        for (int u = 0; u < U; u++)
#pragma unroll
            for (int s = 0; s < 7; s++) acc[k][u][s] = 0.0f;

    int e0 = off[n], e1 = off[n + 1];
    for (int base = e0; base < e1; base += 64) {
        int cnt = min(64, e1 - base);
        __syncthreads();
        if (tid < cnt) {
            int e = perm[base + tid];
            sSrc[tid] = srcArr[e];
            float u0 = ea[e * 3 + 0], u1 = ea[e * 3 + 1], u2 = ea[e * 3 + 2];
            float w0 = u0 * sA[0] + u1 * sA[3] + u2 * sA[6];
            float w1 = u0 * sA[1] + u1 * sA[4] + u2 * sA[7];
            float w2 = u0 * sA[2] + u1 * sA[5] + u2 * sA[8];
            float m = fmaxf(w0, fmaxf(w1, w2));
            float q0 = __expf(w0 - m), q1 = __expf(w1 - m), q2 = __expf(w2 - m);
            float qi = 1.0f / (q0 + q1 + q2);
            sEw[tid * 3 + 0] = q0 * qi;
            sEw[tid * 3 + 1] = q1 * qi;
            sEw[tid * 3 + 2] = q2 * qi;
        }
        __syncthreads();
        for (int j = 0; j < cnt; j++) {
            float q0 = sEw[j * 3 + 0], q1 = sEw[j * 3 + 1], q2 = sEw[j * 3 + 2];
            const float* xp = xin + (long)(b * Nn + sSrc[j]) * (CIN * TT);
#pragma unroll
            for (int u = 0; u < U; u++) {
#pragma unroll
                for (int s = 0; s < 7; s++) {
                    int t = tx + 32 * s;
                    float v = xp[(ty + 8 * u) * TT + (t < TT ? t : 0)];
                    acc[0][u][s] += q0 * v;
                    acc[1][u][s] += q1 * v;
                    acc[2][u][s] += q2 * v;
                }
            }
        }
    }

    // ---- build cat = [G | x] in bf16 hi/lo smem ----
    float inv = inv_cnt[n];
    __syncthreads();
    __nv_bfloat16* chi = (__nv_bfloat16*)(dsm + chi_o);
    __nv_bfloat16* clo = (__nv_bfloat16*)(dsm + clo_o);
#pragma unroll
    for (int k = 0; k < 3; k++)
#pragma unroll
        for (int u = 0; u < U; u++)
#pragma unroll
            for (int s = 0; s < 7; s++) {
                int t = tx + 32 * s;
                if (t < TT) {
                    int row = k * CIN + ty + 8 * u;
                    float v = acc[k][u][s] * inv;
                    __nv_bfloat16 hi = __float2bfloat16(v);
                    chi[row * TT + t] = hi;
                    clo[row * TT + t] = __float2bfloat16(v - __bfloat162float(hi));
                }
            }
    {
        const float* xp = xin + (long)(b * Nn + n) * (CIN * TT);
#pragma unroll
        for (int u = 0; u < U; u++)
#pragma unroll
            for (int s = 0; s < 7; s++) {
                int t = tx + 32 * s;
                if (t < TT) {
                    int c = ty + 8 * u;
                    float v = xp[c * TT + t];
                    int row = 3 * CIN + c;
                    __nv_bfloat16 hi = __float2bfloat16(v);
                    chi[row * TT + t] = hi;
                    clo[row * TT + t] = __float2bfloat16(v - __bfloat162float(hi));
                }
            }
    }
    __syncthreads();

    // ---- combine on tensor cores: out[COUT x 200] = Wt @ cat, bf16x3 ----
    int mt = w % MT;
    int ntStart = w / MT;
    constexpr int NTSTRIDE = 8 / MT;

    uint32_t ah[KQ][4], al[KQ][4];
#pragma unroll
    for (int kq = 0; kq < KQ; kq++) {
        int kc = kq >> 2, ks = kq & 3;
        uint32_t offA = kc * COUT * 128 +
                        SW128((mt * 16 + (lane & 15)) * 128 + ks * 32 + (lane >> 4) * 16);
        LDM4(ah[kq], sb + sWh_o + offA);
        LDM4(al[kq], sb + sWl_o + offA);
    }

    long obase = (long)(b * Nn + n) * (COUT * TT);
    int o0 = mt * 16 + (lane >> 2);
    float bb0 = sbias[o0], bb1 = sbias[o0 + 8];
    for (int nt = ntStart; nt < 25; nt += NTSTRIDE) {
        float c[4] = {0.f, 0.f, 0.f, 0.f};
#pragma unroll
        for (int kq = 0; kq < KQ; kq++) {
            uint32_t offB = (uint32_t)(kq * 16 + (lane & 15)) * 400 + nt * 16;
            uint32_t bh[2], bl[2];
            LDM2T(bh, sb + chi_o + offB);
            LDM2T(bl, sb + clo_o + offB);
            MMA_BF16(c, ah[kq], bh);
            MMA_BF16(c, ah[kq], bl);
            MMA_BF16(c, al[kq], bh);
        }
        int t0 = nt * 8 + (lane & 3) * 2;
        float v0 = c[0] + bb0; v0 = v0 > 0.f ? v0 : expm1f(v0);
        float v1 = c[1] + bb0; v1 = v1 > 0.f ? v1 : expm1f(v1);
        __nv_bfloat16 h0 = __float2bfloat16(v0), h1 = __float2bfloat16(v1);
        *(uint32_t*)&Bh[obase + (long)o0 * TT + t0] =
            (uint32_t)__bfloat16_as_ushort(h0) | ((uint32_t)__bfloat16_as_ushort(h1) << 16);
        *(uint32_t*)&Bl[obase + (long)o0 * TT + t0] =
            pack_bf2(v0 - __bfloat162float(h0), v1 - __bfloat162float(h1));
        float v2 = c[2] + bb1; v2 = v2 > 0.f ? v2 : expm1f(v2);
        float v3 = c[3] + bb1; v3 = v3 > 0.f ? v3 : expm1f(v3);
        __nv_bfloat16 h2 = __float2bfloat16(v2), h3 = __float2bfloat16(v3);
        *(uint32_t*)&Bh[obase + (long)(o0 + 8) * TT + t0] =
            (uint32_t)__bfloat16_as_ushort(h2) | ((uint32_t)__bfloat16_as_ushort(h3) << 16);
        *(uint32_t*)&Bl[obase + (long)(o0 + 8) * TT + t0] =
            pack_bf2(v2 - __bfloat162float(h2), v3 - __bfloat162float(h3));
    }
}

// ------- bf16x3 GEMM (R8): Kc=64, 96KB, cp.async double-buffered -------------
__global__ __launch_bounds__(256)
void mma_gemm_kernel(const __nv_bfloat16* __restrict__ Ahi, const __nv_bfloat16* __restrict__ Alo,
                     const __nv_bfloat16* __restrict__ Bhi, const __nv_bfloat16* __restrict__ Blo,
                     float* __restrict__ C, int Mout, int K, int F) {
    extern __shared__ __align__(16) char smem[];
    const int BUF = 49152;
    const int OFF_AH = 0, OFF_AL = 16384, OFF_BH = 32768, OFF_BL = 40960;
    uint32_t sbase = smem_u32(smem);
    int tid = threadIdx.x, lane = tid & 31, w = tid >> 5;
    int mw = w & 1, fw = w >> 1;
    int f0 = blockIdx.x * 64, row0 = blockIdx.y * 128, b = blockIdx.z;

    const __nv_bfloat16* BhB = Bhi + (long)b * K * F;
    const __nv_bfloat16* BlB = Blo + (long)b * K * F;

    float acc[4][2][4];
#pragma unroll
    for (int mt = 0; mt < 4; mt++)
#pragma unroll
        for (int nt = 0; nt < 2; nt++)
#pragma unroll
            for (int q = 0; q < 4; q++) acc[mt][nt][q] = 0.0f;

    int r = tid >> 3, cb = (tid & 7) * 16;
    int nchunk = K >> 6;

#define STAGE(bo, k0)                                                              \
    do {                                                                           \
        _Pragma("unroll")                                                          \
        for (int i = 0; i < 4; i++) {                                              \
            int rr = r + i * 32;                                                   \
            uint32_t so = SW128(rr * 128 + cb);                                    \
            CP16(sbase + (bo) + OFF_AH + so,                                       \
                 (const char*)&Ahi[(long)(row0 + rr) * K + (k0) + (cb >> 1)]);     \
            CP16(sbase + (bo) + OFF_AL + so,                                       \
                 (const char*)&Alo[(long)(row0 + rr) * K + (k0) + (cb >> 1)]);     \
        }                                                                          \
        _Pragma("unroll")                                                          \
        for (int i = 0; i < 2; i++) {                                              \
            int rr = r + i * 32;                                                   \
            uint32_t so = SW128(rr * 128 + cb);                                    \
            long gi = (long)((k0) + rr) * F + f0 + (cb >> 1);                      \
            CP16(sbase + (bo) + OFF_BH + so, (const char*)&BhB[gi]);               \
            CP16(sbase + (bo) + OFF_BL + so, (const char*)&BlB[gi]);               \
        }                                                                          \
    } while (0)

    STAGE(0, 0);
    CP_COMMIT;

    int buf = 0;
    for (int kc = 0; kc < nchunk; kc++) {
        CP_WAIT0;
        __syncthreads();
        if (kc + 1 < nchunk) {
            STAGE((buf ^ 1) * BUF, (kc + 1) << 6);
            CP_COMMIT;
        }
        int bo = buf * BUF;
#pragma unroll
        for (int ks = 0; ks < 4; ks++) {
            uint32_t ah[4][4], al[4][4], bh[2][2], bl[2][2];
#pragma unroll
            for (int mt = 0; mt < 4; mt++) {
                uint32_t off = SW128((mw * 64 + mt * 16 + (lane & 15)) * 128 +
                                     ks * 32 + (lane >> 4) * 16);
                LDM4(ah[mt], sbase + bo + OFF_AH + off);
                LDM4(al[mt], sbase + bo + OFF_AL + off);
            }
#pragma unroll
            for (int nt = 0; nt < 2; nt++) {
                uint32_t off = SW128((ks * 16 + (lane & 15)) * 128 + fw * 32 + nt * 16);
                LDM2T(bh[nt], sbase + bo + OFF_BH + off);
                LDM2T(bl[nt], sbase + bo + OFF_BL + off);
            }
#pragma unroll
            for (int mt = 0; mt < 4; mt++) {
#pragma unroll
                for (int nt = 0; nt < 2; nt++) {
                    MMA_BF16(acc[mt][nt], ah[mt], bh[nt]);
                    MMA_BF16(acc[mt][nt], ah[mt], bl[nt]);
                    MMA_BF16(acc[mt][nt], al[mt], bh[nt]);
                }
            }
        }
        __syncthreads();
        buf ^= 1;
    }
#undef STAGE

#pragma unroll
    for (int mt = 0; mt < 4; mt++) {
        int gr = row0 + mw * 64 + mt * 16 + (lane >> 2);
#pragma unroll
        for (int nt = 0; nt < 2; nt++) {
            int gc = f0 + fw * 16 + nt * 8 + (lane & 3) * 2;
            if (gr < Mout)
                *(float2*)&C[((long)b * Mout + gr) * F + gc] =
                    make_float2(acc[mt][nt][0], acc[mt][nt][1]);
            if (gr + 8 < Mout)
                *(float2*)&C[((long)b * Mout + gr + 8) * F + gc] =
                    make_float2(acc[mt][nt][2], acc[mt][nt][3]);
        }
    }
}

// ------------ fused head: elu(p3@W1+b1) -> tanh(.@W2+b2), smem hm -----------
__global__ __launch_bounds__(256)
void head_kernel(const float* __restrict__ p3,
                 const float* __restrict__ f1w, const float* __restrict__ f1b,
                 const float* __restrict__ f2w, const float* __restrict__ f2b,
                 float* __restrict__ out, int Nn) {
    extern __shared__ __align__(16) float ds[];
    float* w1 = ds;
    float* w2 = w1 + 8192;
    float* b1s = w2 + 8192;
    float* b2s = b1s + 128;
    float* hmS = b2s + 64;
    int n = blockIdx.x, b = blockIdx.y;
    int tid = threadIdx.x, tx = tid & 31, ty = tid >> 5;
    for (int q = tid; q < 8192; q += 256) { w1[q] = f1w[q]; w2[q] = f2w[q]; }
    if (tid < 128) b1s[tid] = f1b[tid];
    if (tid < 64) b2s[tid] = f2b[tid];
    __syncthreads();

    const float* xp = p3 + (long)(b * Nn + n) * (64 * TT);
    float* op = out + (long)(b * Nn + n) * (64 * TT);

    for (int tz = 0; tz < 2; tz++) {
        int toff = tz * 100;
        float acc1[16][4];
#pragma unroll
        for (int u = 0; u < 16; u++)
#pragma unroll
            for (int s = 0; s < 4; s++) acc1[u][s] = 0.0f;
#pragma unroll 4
        for (int j = 0; j < 64; j++) {
            float xr[4];
#pragma unroll
            for (int s = 0; s < 4; s++) {
                int t = tx + 32 * s;
                xr[s] = xp[j * TT + toff + (t < 100 ? t : 0)];
            }
#pragma unroll
            for (int u = 0; u < 16; u++) {
                float w = w1[j * 128 + ty + 8 * u];
#pragma unroll
                for (int s = 0; s < 4; s++) acc1[u][s] += w * xr[s];
            }
        }
        __syncthreads();
#pragma unroll
        for (int u = 0; u < 16; u++) {
            int o = ty + 8 * u;
            float bb = b1s[o];
#pragma unroll
            for (int s = 0; s < 4; s++) {
                int t = tx + 32 * s;
                if (t < 100) {
                    float v = acc1[u][s] + bb;
                    v = v > 0.0f ? v : expm1f(v);
                    hmS[o * 100 + t] = v;
                }
            }
        }
        __syncthreads();
        float acc2[8][4];
#pragma unroll
        for (int u = 0; u < 8; u++)
#pragma unroll
            for (int s = 0; s < 4; s++) acc2[u][s] = 0.0f;
#pragma unroll 4
        for (int j = 0; j < 128; j++) {
            float xr[4];
#pragma unroll
            for (int s = 0; s < 4; s++) {
                int t = tx + 32 * s;
                xr[s] = hmS[j * 100 + (t < 100 ? t : 0)];
            }
#pragma unroll
            for (int u = 0; u < 8; u++) {
                float w = w2[j * 64 + ty + 8 * u];
#pragma unroll
                for (int s = 0; s < 4; s++) acc2[u][s] += w * xr[s];
            }
        }
#pragma unroll
        for (int u = 0; u < 8; u++) {
            int o = ty + 8 * u;
            float bb = b2s[o];
#pragma unroll
            for (int s = 0; s < 4; s++) {
                int t = tx + 32 * s;
                if (t < 100) op[o * TT + toff + t] = tanhf(acc2[u][s] + bb);
            }
        }
        __syncthreads();
    }
}

// -------------------------------- launch ------------------------------------
#define GETSYM(var, sym)                                       \
    do {                                                       \
        void* _p = nullptr;                                    \
        cudaGetSymbolAddress(&_p, sym);                        \
        var = (decltype(var))_p;                               \
    } while (0)

extern "C" void kernel_launch(void* const* d_in, const int* in_sizes, int n_in,
                              void* d_out, int out_size) {
    (void)in_sizes; (void)n_in; (void)out_size;
    const float* x   = (const float*)d_in[0];
    const int*   ei0 = (const int*)d_in[1];
    const float* ea0 = (const float*)d_in[2];
    const int*   ei1 = (const int*)d_in[3];
    const float* ea1 = (const float*)d_in[4];
    const int*   ei2 = (const int*)d_in[5];
    const float* ea2 = (const float*)d_in[6];
    const float* A1  = (const float*)d_in[7];
    const float* Wk1 = (const float*)d_in[8];
    const float* Wr1 = (const float*)d_in[9];
    const float* b1  = (const float*)d_in[10];
    const float* A2  = (const float*)d_in[11];
    const float* Wk2 = (const float*)d_in[12];
    const float* Wr2 = (const float*)d_in[13];
    const float* b2  = (const float*)d_in[14];
    const float* A3  = (const float*)d_in[15];
    const float* Wk3 = (const float*)d_in[16];
    const float* Wr3 = (const float*)d_in[17];
    const float* b3  = (const float*)d_in[18];
    const float* P01 = (const float*)d_in[19];
    const float* P12 = (const float*)d_in[20];
    const float* P23 = (const float*)d_in[21];
    const float* f1w = (const float*)d_in[22];
    const float* f1b = (const float*)d_in[23];
    const float* f2w = (const float*)d_in[24];
    const float* f2b = (const float*)d_in[25];

    const int N0 = 2048, N1 = 512, N2 = 128, N3 = 64;

    float *p1, *p2, *p3;
    __nv_bfloat16 *A1h, *A1l, *A2h, *A2l, *A3h, *A3l, *Bh, *Bl;
    __nv_bfloat16 *Wt1h, *Wt1l, *Wt2h, *Wt2l;
    int *off0, *perm0, *off1, *perm1, *off2, *perm2;
    float *inv0, *inv1, *inv2;
    GETSYM(p1, g_p1); GETSYM(p2, g_p2); GETSYM(p3, g_p3);
    GETSYM(A1h, g_A1h); GETSYM(A1l, g_A1l);
    GETSYM(A2h, g_A2h); GETSYM(A2l, g_A2l);
    GETSYM(A3h, g_A3h); GETSYM(A3l, g_A3l);
    GETSYM(Bh, g_Bh); GETSYM(Bl, g_Bl);
    GETSYM(Wt1h, g_Wt1h); GETSYM(Wt1l, g_Wt1l);
    GETSYM(Wt2h, g_Wt2h); GETSYM(Wt2l, g_Wt2l);
    GETSYM(off0, g_off0); GETSYM(perm0, g_perm0);
    GETSYM(off1, g_off1); GETSYM(perm1, g_perm1);
    GETSYM(off2, g_off2); GETSYM(perm2, g_perm2);
    GETSYM(inv0, g_inv0); GETSYM(inv1, g_inv1); GETSYM(inv2, g_inv2);

    const int SMEM_GEMM = 98304;
    cudaFuncSetAttribute(mma_gemm_kernel, cudaFuncAttributeMaxDynamicSharedMemorySize,
                         SMEM_GEMM);
    // gcnf1: Wt 2*1*32*128 + cat 2*64*400 + bias
    const int SMEM_F1 = 2 * 1 * 32 * 128 + 2 * 64 * 400 + 32 * 4;
    // gcnf2: Wt 2*2*64*128 + cat 2*128*400 + bias
    const int SMEM_F2 = 2 * 2 * 64 * 128 + 2 * 128 * 400 + 64 * 4;
    cudaFuncSetAttribute((const void*)gcnf_kernel<16, 32>,
                         cudaFuncAttributeMaxDynamicSharedMemorySize, SMEM_F1);
    cudaFuncSetAttribute((const void*)gcnf_kernel<32, 64>,
                         cudaFuncAttributeMaxDynamicSharedMemorySize, SMEM_F2);
    const int SMEM_HEAD = (8192 + 8192 + 128 + 64 + 12800) * 4;
    cudaFuncSetAttribute(head_kernel, cudaFuncAttributeMaxDynamicSharedMemorySize,
                         SMEM_HEAD);

    // ---- setup: CSR (3 blocks) + splitA + Wt, one launch ----
    const long SPLIT_TOT = 512L * 2048 + 128 * 512 + 128 * 128 + 32 * 64 + 2 * 64 * 64;
    setup_kernel<<<3 + (int)((SPLIT_TOT + 1023) / 1024), 1024>>>(
        ei0, ei1, ei2, off0, perm0, inv0, off1, perm1, inv1, off2, perm2, inv2,
        P01, P12, P23, A1h, A1l, A2h, A2l, A3h, A3l,
        Wk2, Wr2, Wk3, Wr3, Wt1h, Wt1l, Wt2h, Wt2l);

    // ---- level 0->1 GCN ----
    gcn1_kernel<<<N0, 256>>>(x, ea0, A1, Wk1, Wr1, b1, ei0, off0, perm0, inv0, Bh, Bl);

    // ---- pool1: M=512, K=2048, F=3200 ----
    mma_gemm_kernel<<<dim3(3200 / 64, 512 / 128, 2), 256, SMEM_GEMM>>>(
        A1h, A1l, Bh, Bl, p1, 512, 2048, 3200);

    // ---- level 1->2 GCN (scalar gather + tensor-core combine) ----
    gcnf_kernel<16, 32><<<dim3(N1, 2), 256, SMEM_F1>>>(
        p1, ea1, A2, Wt1h, Wt1l, b2, ei1, off1, perm1, inv1, Bh, Bl, N1);

    // ---- pool2: M=128, K=512, F=6400 ----
    mma_gemm_kernel<<<dim3(6400 / 64, 1, 2), 256, SMEM_GEMM>>>(
        A2h, A2l, Bh, Bl, p2, 128, 512, 6400);

    // ---- level 2->3 GCN ----
    gcnf_kernel<32, 64><<<dim3(N2, 2), 256, SMEM_F2>>>(
        p2, ea2, A3, Wt2h, Wt2l, b3, ei2, off2, perm2, inv2, Bh, Bl, N2);

    // ---- pool3: M=64 (padded 128), K=128, F=12800 ----
    mma_gemm_kernel<<<dim3(12800 / 64, 1, 2), 256, SMEM_GEMM>>>(
        A3h, A3l, Bh, Bl, p3, 64, 128, 12800);

    // ---- fused head ----
    head_kernel<<<dim3(N3, 2), 256, SMEM_HEAD>>>(
        p3, f1w, f1b, f2w, f2b, (float*)d_out, N3);
}

// round 15
// speedup vs baseline: 1.2826x; 1.0262x over previous
#include <cuda_runtime.h>
#include <cuda_bf16.h>
#include <cstdint>

// ============================================================================
// Graph_ODE_RNN — 8-launch pipeline (R8 config + gcnf Wt-from-global):
//  [csr+splitA+Wt] -> gcn1 -> pool1 -> gcnf1 -> pool2 -> gcnf2 -> pool3 -> head
//  gcnf: scalar gather + tensor-core combine; combine A-fragments loaded
//        directly from global (no Wt smem) -> higher occupancy.
//  pool GEMM: bf16x3 mma.sync, Kc=64, 96KB cp.async double buffer.
// ============================================================================

#define TT 200

// ---------------- static scratch (no allocation allowed) -------------------
__device__ float g_p1[2 * 512 * 16 * TT];
__device__ float g_p2[2 * 128 * 32 * TT];
__device__ float g_p3[2 * 64 * 64 * TT];

__device__ __nv_bfloat16 g_A1h[512 * 2048], g_A1l[512 * 2048];
__device__ __nv_bfloat16 g_A2h[128 * 512],  g_A2l[128 * 512];
__device__ __nv_bfloat16 g_A3h[128 * 128],  g_A3l[128 * 128];  // M padded 64->128
__device__ __nv_bfloat16 g_Bh[2 * 2048 * 3200], g_Bl[2 * 2048 * 3200];

// combine weights W^T, bf16 hi/lo, chunk layout [kc][m][64]
__device__ __nv_bfloat16 g_Wt1h[32 * 64],  g_Wt1l[32 * 64];
__device__ __nv_bfloat16 g_Wt2h[2 * 64 * 64], g_Wt2l[2 * 64 * 64];

__device__ int g_off0[2049], g_perm0[16384];
__device__ int g_off1[513],  g_perm1[8192];
__device__ int g_off2[129],  g_perm2[2048];
__device__ float g_inv0[2048], g_inv1[512], g_inv2[128];

// ---------------------------- helpers ---------------------------------------
__device__ __forceinline__ uint32_t smem_u32(const void* p) {
    uint32_t a;
    asm("{ .reg .u64 t; cvta.to.shared.u64 t, %1; cvt.u32.u64 %0, t; }"
        : "=r"(a) : "l"(p));
    return a;
}

#define SW128(x) ((x) ^ (((x) >> 3) & 0x70))

#define LDM4(r, addr)                                                            \
    asm volatile("ldmatrix.sync.aligned.m8n8.x4.shared.b16 {%0,%1,%2,%3}, [%4];" \
                 : "=r"((r)[0]), "=r"((r)[1]), "=r"((r)[2]), "=r"((r)[3])        \
                 : "r"(addr))

#define LDM2T(r, addr)                                                           \
    asm volatile("ldmatrix.sync.aligned.m8n8.x2.trans.shared.b16 {%0,%1}, [%2];" \
                 : "=r"((r)[0]), "=r"((r)[1]) : "r"(addr))

#define MMA_BF16(c, a, bb)                                                       \
    asm volatile("mma.sync.aligned.m16n8k16.row.col.f32.bf16.bf16.f32 "          \
                 "{%0,%1,%2,%3}, {%4,%5,%6,%7}, {%8,%9}, {%0,%1,%2,%3};"         \
                 : "+f"((c)[0]), "+f"((c)[1]), "+f"((c)[2]), "+f"((c)[3])        \
                 : "r"((a)[0]), "r"((a)[1]), "r"((a)[2]), "r"((a)[3]),           \
                   "r"((bb)[0]), "r"((bb)[1]))

#define CP16(dst, src)                                                           \
    asm volatile("cp.async.cg.shared.global [%0], [%1], 16;" :: "r"(dst), "l"(src))
#define CP_COMMIT asm volatile("cp.async.commit_group;" ::: "memory")
#define CP_WAIT0  asm volatile("cp.async.wait_group 0;" ::: "memory")

__device__ __forceinline__ uint32_t pack_bf2(float a, float b) {
    __nv_bfloat16 ha = __float2bfloat16(a), hb = __float2bfloat16(b);
    return (uint32_t)__bfloat16_as_ushort(ha) |
           ((uint32_t)__bfloat16_as_ushort(hb) << 16);
}

// -------------- merged setup: 3 CSR blocks + split/Wt blocks ----------------
__global__ __launch_bounds__(1024)
void setup_kernel(const int* e0, const int* e1, const int* e2,
                  int* o0, int* p0, float* v0,
                  int* o1, int* p1, float* v1,
                  int* o2, int* p2, float* v2,
                  const float* __restrict__ P01, const float* __restrict__ P12,
                  const float* __restrict__ P23,
                  __nv_bfloat16* A1h, __nv_bfloat16* A1l,
                  __nv_bfloat16* A2h, __nv_bfloat16* A2l,
                  __nv_bfloat16* A3h, __nv_bfloat16* A3l,
                  const float* __restrict__ Wk2, const float* __restrict__ Wr2,
                  const float* __restrict__ Wk3, const float* __restrict__ Wr3,
                  __nv_bfloat16* Wt1h, __nv_bfloat16* Wt1l,
                  __nv_bfloat16* Wt2h, __nv_bfloat16* Wt2l) {
    int tid = threadIdx.x;
    if (blockIdx.x >= 3) {
        const long S1 = 512 * 2048, S2 = 128 * 512, S3 = 128 * 128;
        const long W1 = 32 * 64, W2 = 2 * 64 * 64;
        long i = (long)(blockIdx.x - 3) * 1024 + tid;
        float v; __nv_bfloat16 *H, *L; long o;
        if (i < S1) { o = i; v = P01[o]; H = A1h; L = A1l; }
        else if (i < S1 + S2) { o = i - S1; v = P12[o]; H = A2h; L = A2l; }
        else if (i < S1 + S2 + S3) {
            o = i - S1 - S2;
            v = ((o >> 7) < 64) ? P23[o] : 0.0f;
            H = A3h; L = A3l;
        } else if (i < S1 + S2 + S3 + W1) {
            o = i - S1 - S2 - S3;
            int m = (int)(o >> 6), kk = (int)(o & 63);
            v = (kk < 48) ? Wk2[kk * 32 + m] : Wr2[(kk - 48) * 32 + m];
            H = Wt1h; L = Wt1l;
        } else if (i < S1 + S2 + S3 + W1 + W2) {
            o = i - S1 - S2 - S3 - W1;
            int kc = (int)(o >> 12), rem = (int)(o & 4095);
            int m = rem >> 6, kk = rem & 63;
            int j = kc * 64 + kk;
            v = (j < 96) ? Wk3[j * 64 + m] : Wr3[(j - 96) * 64 + m];
            H = Wt2h; L = Wt2l;
        } else return;
        __nv_bfloat16 hi = __float2bfloat16(v);
        H[o] = hi;
        L[o] = __float2bfloat16(v - __bfloat162float(hi));
        return;
    }
    // ---- CSR part: one block per level ----
    __shared__ int sa[2048];
    __shared__ int sb[2048];
    __shared__ int scur[2048];
    int lvl = blockIdx.x;
    const int* dst = lvl == 0 ? e0 + 16384 : (lvl == 1 ? e1 + 8192 : e2 + 2048);
    int E = lvl == 0 ? 16384 : (lvl == 1 ? 8192 : 2048);
    int N = lvl == 0 ? 2048 : (lvl == 1 ? 512 : 128);
    int* off = lvl == 0 ? o0 : (lvl == 1 ? o1 : o2);
    int* perm = lvl == 0 ? p0 : (lvl == 1 ? p1 : p2);
    float* inv = lvl == 0 ? v0 : (lvl == 1 ? v1 : v2);

    for (int q = tid; q < 2048; q += 1024) sa[q] = 0;
    __syncthreads();
    for (int i = tid; i < E; i += 1024) atomicAdd(&sa[dst[i]], 1);
    __syncthreads();
    for (int q = tid; q < 2048; q += 1024) {
        int dg = sa[q];
        sb[q] = dg;
        if (q < N) inv[q] = 1.0f / (float)(dg > 0 ? dg : 1);
    }
    __syncthreads();
    int* pc = sa;
    int* pn = scur;
    for (int d = 1; d < 2048; d <<= 1) {
        for (int q = tid; q < 2048; q += 1024) {
            int v = pc[q];
            if (q >= d) v += pc[q - d];
            pn[q] = v;
        }
        __syncthreads();
        int* t = pc; pc = pn; pn = t;
    }
    for (int q = tid; q < N; q += 1024) {
        int o = (q == 0) ? 0 : pc[q - 1];
        off[q] = o;
        pn[q] = o;
    }
    if (tid == 0) off[N] = pc[N - 1];
    __syncthreads();
    for (int i = tid; i < E; i += 1024) {
        int p = atomicAdd(&pn[dst[i]], 1);
        perm[p] = i;
    }
    __syncthreads();
    for (int n = tid; n < N; n += 1024) {
        int a = (n == 0) ? 0 : pc[n - 1];
        int b = pc[n];
        for (int k = a + 1; k < b; k++) {
            int v = perm[k];
            int j = k - 1;
            while (j >= a && perm[j] > v) { perm[j + 1] = perm[j]; j--; }
            perm[j + 1] = v;
        }
    }
}

// ------- level-1 GCN (both batches per block, staged edge weights) ----------
__global__ __launch_bounds__(256)
void gcn1_kernel(const float* __restrict__ x, const float* __restrict__ ea,
                 const float* __restrict__ Amat,
                 const float* __restrict__ Wk, const float* __restrict__ Wr,
                 const float* __restrict__ bias,
                 const int* __restrict__ srcArr, const int* __restrict__ off,
                 const int* __restrict__ perm, const float* __restrict__ inv_cnt,
                 __nv_bfloat16* __restrict__ Bh, __nv_bfloat16* __restrict__ Bl) {
    __shared__ float sA[9];
    __shared__ float sW[80];
    __shared__ int sSrc[64];
    __shared__ float sEw[64 * 3];
    const int N0 = 2048;
    int n = blockIdx.x;
    int t = threadIdx.x;
    if (t < 9) sA[t] = Amat[t];
    if (t < 48) sW[t] = Wk[t];
    else if (t < 64) sW[t] = Wr[t - 48];
    else if (t < 80) sW[t] = bias[t - 64];
    __syncthreads();

    float a0[3] = {0.f, 0.f, 0.f};
    float a1[3] = {0.f, 0.f, 0.f};
    int e0 = off[n], e1 = off[n + 1];
    for (int base = e0; base < e1; base += 64) {
        int cnt = min(64, e1 - base);
        __syncthreads();
        if (t < cnt) {
            int e = perm[base + t];
            sSrc[t] = srcArr[e];
            float u0 = ea[e * 3 + 0], u1 = ea[e * 3 + 1], u2 = ea[e * 3 + 2];
            float w0 = u0 * sA[0] + u1 * sA[3] + u2 * sA[6];
            float w1 = u0 * sA[1] + u1 * sA[4] + u2 * sA[7];
            float w2 = u0 * sA[2] + u1 * sA[5] + u2 * sA[8];
            float m = fmaxf(w0, fmaxf(w1, w2));
            float q0 = __expf(w0 - m), q1 = __expf(w1 - m), q2 = __expf(w2 - m);
            float qi = 1.0f / (q0 + q1 + q2);
            sEw[t * 3 + 0] = q0 * qi;
            sEw[t * 3 + 1] = q1 * qi;
            sEw[t * 3 + 2] = q2 * qi;
        }
        __syncthreads();
        if (t < TT) {
#pragma unroll 2
            for (int j = 0; j < cnt; j++) {
                int src = sSrc[j];
                float w0 = sEw[j * 3 + 0], w1 = sEw[j * 3 + 1], w2 = sEw[j * 3 + 2];
                float va = x[src * TT + t];
                float vb = x[(N0 + src) * TT + t];
                a0[0] += w0 * va; a0[1] += w1 * va; a0[2] += w2 * va;
                a1[0] += w0 * vb; a1[1] += w1 * vb; a1[2] += w2 * vb;
            }
        }
    }
    if (t >= TT) return;
    float inv = inv_cnt[n];
#pragma unroll
    for (int k = 0; k < 3; k++) { a0[k] *= inv; a1[k] *= inv; }
    float xo0 = x[n * TT + t];
    float xo1 = x[(N0 + n) * TT + t];
    long base0 = ((long)n * 16) * TT + t;
    long base1 = ((long)(N0 + n) * 16) * TT + t;
#pragma unroll
    for (int o = 0; o < 16; o++) {
        float v = a0[0] * sW[o] + a0[1] * sW[16 + o] + a0[2] * sW[32 + o] +
                  xo0 * sW[48 + o] + sW[64 + o];
        v = v > 0.0f ? v : expm1f(v);
        __nv_bfloat16 hi = __float2bfloat16(v);
        Bh[base0 + (long)o * TT] = hi;
        Bl[base0 + (long)o * TT] = __float2bfloat16(v - __bfloat162float(hi));
        v = a1[0] * sW[o] + a1[1] * sW[16 + o] + a1[2] * sW[32 + o] +
            xo1 * sW[48 + o] + sW[64 + o];
        v = v > 0.0f ? v : expm1f(v);
        hi = __float2bfloat16(v);
        Bh[base1 + (long)o * TT] = hi;
        Bl[base1 + (long)o * TT] = __float2bfloat16(v - __bfloat162float(hi));
    }
}

// ----- fused GCN level: scalar gather + tensor-core combine -----------------
// Combine A-fragments loaded directly from global Wt (no smem staging).
// dyn smem: [0, K4*400) chi | [K4*400, 2*K4*400) clo | sbias
template <int CIN, int COUT>
__global__ __launch_bounds__(256)
void gcnf_kernel(const float* __restrict__ xin, const float* __restrict__ ea,
                 const float* __restrict__ Amat,
                 const __nv_bfloat16* __restrict__ Wth,
                 const __nv_bfloat16* __restrict__ Wtl,
                 const float* __restrict__ bias,
                 const int* __restrict__ srcArr, const int* __restrict__ off,
                 const int* __restrict__ perm, const float* __restrict__ inv_cnt,
                 __nv_bfloat16* __restrict__ Bh, __nv_bfloat16* __restrict__ Bl, int Nn) {
    constexpr int K4 = 4 * CIN;
    constexpr int MT = COUT / 16;
    constexpr int KQ = K4 / 16;
    extern __shared__ __align__(16) char dsm[];
    const uint32_t chi_o = 0;
    const uint32_t clo_o = K4 * 400;
    float* sbias = (float*)(dsm + 2 * K4 * 400);
    uint32_t sb = smem_u32(dsm);
    __shared__ float sA[9];
    __shared__ int sSrc[64];
    __shared__ float sEw[64 * 3];

    int n = blockIdx.x, b = blockIdx.y;
    int tid = threadIdx.x, lane = tid & 31, w = tid >> 5;
    int tx = lane, ty = w;
    if (tid < 9) sA[tid] = Amat[tid];
    if (tid < COUT) sbias[tid] = bias[tid];
    __syncthreads();

    // ---- gather (scalar form): acc[k][u][s], (ch = ty+8u, t = tx+32s) ----
    constexpr int U = CIN / 8;
    float acc[3][U][7];
#pragma unroll
    for (int k = 0; k < 3; k++)
#pragma unroll
        for (int u = 0; u < U; u++)
#pragma unroll
            for (int s = 0; s < 7; s++) acc[k][u][s] = 0.0f;

    int e0 = off[n], e1 = off[n + 1];
    for (int base = e0; base < e1; base += 64) {
        int cnt = min(64, e1 - base);
        __syncthreads();
        if (tid < cnt) {
            int e = perm[base + tid];
            sSrc[tid] = srcArr[e];
            float u0 = ea[e * 3 + 0], u1 = ea[e * 3 + 1], u2 = ea[e * 3 + 2];
            float w0 = u0 * sA[0] + u1 * sA[3] + u2 * sA[6];
            float w1 = u0 * sA[1] + u1 * sA[4] + u2 * sA[7];
            float w2 = u0 * sA[2] + u1 * sA[5] + u2 * sA[8];
            float m = fmaxf(w0, fmaxf(w1, w2));
            float q0 = __expf(w0 - m), q1 = __expf(w1 - m), q2 = __expf(w2 - m);
            float qi = 1.0f / (q0 + q1 + q2);
            sEw[tid * 3 + 0] = q0 * qi;
            sEw[tid * 3 + 1] = q1 * qi;
            sEw[tid * 3 + 2] = q2 * qi;
        }
        __syncthreads();
        for (int j = 0; j < cnt; j++) {
            float q0 = sEw[j * 3 + 0], q1 = sEw[j * 3 + 1], q2 = sEw[j * 3 + 2];
            const float* xp = xin + (long)(b * Nn + sSrc[j]) * (CIN * TT);
#pragma unroll
            for (int u = 0; u < U; u++) {
#pragma unroll
                for (int s = 0; s < 7; s++) {
                    int t = tx + 32 * s;
                    float v = xp[(ty + 8 * u) * TT + (t < TT ? t : 0)];
                    acc[0][u][s] += q0 * v;
                    acc[1][u][s] += q1 * v;
                    acc[2][u][s] += q2 * v;
                }
            }
        }
    }

    // ---- build cat = [G | x] in bf16 hi/lo smem ----
    float inv = inv_cnt[n];
    __syncthreads();
    __nv_bfloat16* chi = (__nv_bfloat16*)(dsm + chi_o);
    __nv_bfloat16* clo = (__nv_bfloat16*)(dsm + clo_o);
#pragma unroll
    for (int k = 0; k < 3; k++)
#pragma unroll
        for (int u = 0; u < U; u++)
#pragma unroll
            for (int s = 0; s < 7; s++) {
                int t = tx + 32 * s;
                if (t < TT) {
                    int row = k * CIN + ty + 8 * u;
                    float v = acc[k][u][s] * inv;
                    __nv_bfloat16 hi = __float2bfloat16(v);
                    chi[row * TT + t] = hi;
                    clo[row * TT + t] = __float2bfloat16(v - __bfloat162float(hi));
                }
            }
    {
        const float* xp = xin + (long)(b * Nn + n) * (CIN * TT);
#pragma unroll
        for (int u = 0; u < U; u++)
#pragma unroll
            for (int s = 0; s < 7; s++) {
                int t = tx + 32 * s;
                if (t < TT) {
                    int c = ty + 8 * u;
                    float v = xp[c * TT + t];
                    int row = 3 * CIN + c;
                    __nv_bfloat16 hi = __float2bfloat16(v);
                    chi[row * TT + t] = hi;
                    clo[row * TT + t] = __float2bfloat16(v - __bfloat162float(hi));
                }
            }
    }
    __syncthreads();

    // ---- combine on tensor cores: out[COUT x 200] = Wt @ cat, bf16x3 ----
    // A-fragments straight from global [kc][m][64] layout (L1/L2 cached).
    int mt = w % MT;
    int ntStart = w / MT;
    constexpr int NTSTRIDE = 8 / MT;

    uint32_t ah[KQ][4], al[KQ][4];
    {
        int m0 = mt * 16 + (lane >> 2);
        int kk0 = (lane & 3) * 2;
#pragma unroll
        for (int kq = 0; kq < KQ; kq++) {
            int kc = kq >> 2;
            int kkb = (kq & 3) * 16 + kk0;
            const __nv_bfloat16* bhp = Wth + kc * COUT * 64;
            const __nv_bfloat16* blp = Wtl + kc * COUT * 64;
            ah[kq][0] = *(const uint32_t*)&bhp[m0 * 64 + kkb];
            ah[kq][1] = *(const uint32_t*)&bhp[(m0 + 8) * 64 + kkb];
            ah[kq][2] = *(const uint32_t*)&bhp[m0 * 64 + kkb + 8];
            ah[kq][3] = *(const uint32_t*)&bhp[(m0 + 8) * 64 + kkb + 8];
            al[kq][0] = *(const uint32_t*)&blp[m0 * 64 + kkb];
            al[kq][1] = *(const uint32_t*)&blp[(m0 + 8) * 64 + kkb];
            al[kq][2] = *(const uint32_t*)&blp[m0 * 64 + kkb + 8];
            al[kq][3] = *(const uint32_t*)&blp[(m0 + 8) * 64 + kkb + 8];
        }
    }

    long obase = (long)(b * Nn + n) * (COUT * TT);
    int o0 = mt * 16 + (lane >> 2);
    float bb0 = sbias[o0], bb1 = sbias[o0 + 8];
    for (int nt = ntStart; nt < 25; nt += NTSTRIDE) {
        float c[4] = {0.f, 0.f, 0.f, 0.f};
#pragma unroll
        for (int kq = 0; kq < KQ; kq++) {
            uint32_t offB = (uint32_t)(kq * 16 + (lane & 15)) * 400 + nt * 16;
            uint32_t bh[2], bl[2];
            LDM2T(bh, sb + chi_o + offB);
            LDM2T(bl, sb + clo_o + offB);
            MMA_BF16(c, ah[kq], bh);
            MMA_BF16(c, ah[kq], bl);
            MMA_BF16(c, al[kq], bh);
        }
        int t0 = nt * 8 + (lane & 3) * 2;
        float v0 = c[0] + bb0; v0 = v0 > 0.f ? v0 : expm1f(v0);
        float v1 = c[1] + bb0; v1 = v1 > 0.f ? v1 : expm1f(v1);
        __nv_bfloat16 h0 = __float2bfloat16(v0), h1 = __float2bfloat16(v1);
        *(uint32_t*)&Bh[obase + (long)o0 * TT + t0] =
            (uint32_t)__bfloat16_as_ushort(h0) | ((uint32_t)__bfloat16_as_ushort(h1) << 16);
        *(uint32_t*)&Bl[obase + (long)o0 * TT + t0] =
            pack_bf2(v0 - __bfloat162float(h0), v1 - __bfloat162float(h1));
        float v2 = c[2] + bb1; v2 = v2 > 0.f ? v2 : expm1f(v2);
        float v3 = c[3] + bb1; v3 = v3 > 0.f ? v3 : expm1f(v3);
        __nv_bfloat16 h2 = __float2bfloat16(v2), h3 = __float2bfloat16(v3);
        *(uint32_t*)&Bh[obase + (long)(o0 + 8) * TT + t0] =
            (uint32_t)__bfloat16_as_ushort(h2) | ((uint32_t)__bfloat16_as_ushort(h3) << 16);
        *(uint32_t*)&Bl[obase + (long)(o0 + 8) * TT + t0] =
            pack_bf2(v2 - __bfloat162float(h2), v3 - __bfloat162float(h3));
    }
}

// ------- bf16x3 GEMM (R8): Kc=64, 96KB, cp.async double-buffered -------------
__global__ __launch_bounds__(256)
void mma_gemm_kernel(const __nv_bfloat16* __restrict__ Ahi, const __nv_bfloat16* __restrict__ Alo,
                     const __nv_bfloat16* __restrict__ Bhi, const __nv_bfloat16* __restrict__ Blo,
                     float* __restrict__ C, int Mout, int K, int F) {
    extern __shared__ __align__(16) char smem[];
    const int BUF = 49152;
    const int OFF_AH = 0, OFF_AL = 16384, OFF_BH = 32768, OFF_BL = 40960;
    uint32_t sbase = smem_u32(smem);
    int tid = threadIdx.x, lane = tid & 31, w = tid >> 5;
    int mw = w & 1, fw = w >> 1;
    int f0 = blockIdx.x * 64, row0 = blockIdx.y * 128, b = blockIdx.z;

    const __nv_bfloat16* BhB = Bhi + (long)b * K * F;
    const __nv_bfloat16* BlB = Blo + (long)b * K * F;

    float acc[4][2][4];
#pragma unroll
    for (int mt = 0; mt < 4; mt++)
#pragma unroll
        for (int nt = 0; nt < 2; nt++)
#pragma unroll
            for (int q = 0; q < 4; q++) acc[mt][nt][q] = 0.0f;

    int r = tid >> 3, cb = (tid & 7) * 16;
    int nchunk = K >> 6;

#define STAGE(bo, k0)                                                              \
    do {                                                                           \
        _Pragma("unroll")                                                          \
        for (int i = 0; i < 4; i++) {                                              \
            int rr = r + i * 32;                                                   \
            uint32_t so = SW128(rr * 128 + cb);                                    \
            CP16(sbase + (bo) + OFF_AH + so,                                       \
                 (const char*)&Ahi[(long)(row0 + rr) * K + (k0) + (cb >> 1)]);     \
            CP16(sbase + (bo) + OFF_AL + so,                                       \
                 (const char*)&Alo[(long)(row0 + rr) * K + (k0) + (cb >> 1)]);     \
        }                                                                          \
        _Pragma("unroll")                                                          \
        for (int i = 0; i < 2; i++) {                                              \
            int rr = r + i * 32;                                                   \
            uint32_t so = SW128(rr * 128 + cb);                                    \
            long gi = (long)((k0) + rr) * F + f0 + (cb >> 1);                      \
            CP16(sbase + (bo) + OFF_BH + so, (const char*)&BhB[gi]);               \
            CP16(sbase + (bo) + OFF_BL + so, (const char*)&BlB[gi]);               \
        }                                                                          \
    } while (0)

    STAGE(0, 0);
    CP_COMMIT;

    int buf = 0;
    for (int kc = 0; kc < nchunk; kc++) {
        CP_WAIT0;
        __syncthreads();
        if (kc + 1 < nchunk) {
            STAGE((buf ^ 1) * BUF, (kc + 1) << 6);
            CP_COMMIT;
        }
        int bo = buf * BUF;
#pragma unroll
        for (int ks = 0; ks < 4; ks++) {
            uint32_t ah[4][4], al[4][4], bh[2][2], bl[2][2];
#pragma unroll
            for (int mt = 0; mt < 4; mt++) {
                uint32_t off = SW128((mw * 64 + mt * 16 + (lane & 15)) * 128 +
                                     ks * 32 + (lane >> 4) * 16);
                LDM4(ah[mt], sbase + bo + OFF_AH + off);
                LDM4(al[mt], sbase + bo + OFF_AL + off);
            }
#pragma unroll
            for (int nt = 0; nt < 2; nt++) {
                uint32_t off = SW128((ks * 16 + (lane & 15)) * 128 + fw * 32 + nt * 16);
                LDM2T(bh[nt], sbase + bo + OFF_BH + off);
                LDM2T(bl[nt], sbase + bo + OFF_BL + off);
            }
#pragma unroll
            for (int mt = 0; mt < 4; mt++) {
#pragma unroll
                for (int nt = 0; nt < 2; nt++) {
                    MMA_BF16(acc[mt][nt], ah[mt], bh[nt]);
                    MMA_BF16(acc[mt][nt], ah[mt], bl[nt]);
                    MMA_BF16(acc[mt][nt], al[mt], bh[nt]);
                }
            }
        }
        __syncthreads();
        buf ^= 1;
    }
#undef STAGE

#pragma unroll
    for (int mt = 0; mt < 4; mt++) {
        int gr = row0 + mw * 64 + mt * 16 + (lane >> 2);
#pragma unroll
        for (int nt = 0; nt < 2; nt++) {
            int gc = f0 + fw * 16 + nt * 8 + (lane & 3) * 2;
            if (gr < Mout)
                *(float2*)&C[((long)b * Mout + gr) * F + gc] =
                    make_float2(acc[mt][nt][0], acc[mt][nt][1]);
            if (gr + 8 < Mout)
                *(float2*)&C[((long)b * Mout + gr + 8) * F + gc] =
                    make_float2(acc[mt][nt][2], acc[mt][nt][3]);
        }
    }
}

// ------------ fused head: elu(p3@W1+b1) -> tanh(.@W2+b2), smem hm -----------
__global__ __launch_bounds__(256)
void head_kernel(const float* __restrict__ p3,
                 const float* __restrict__ f1w, const float* __restrict__ f1b,
                 const float* __restrict__ f2w, const float* __restrict__ f2b,
                 float* __restrict__ out, int Nn) {
    extern __shared__ __align__(16) float ds[];
    float* w1 = ds;
    float* w2 = w1 + 8192;
    float* b1s = w2 + 8192;
    float* b2s = b1s + 128;
    float* hmS = b2s + 64;
    int n = blockIdx.x, b = blockIdx.y;
    int tid = threadIdx.x, tx = tid & 31, ty = tid >> 5;
    for (int q = tid; q < 8192; q += 256) { w1[q] = f1w[q]; w2[q] = f2w[q]; }
    if (tid < 128) b1s[tid] = f1b[tid];
    if (tid < 64) b2s[tid] = f2b[tid];
    __syncthreads();

    const float* xp = p3 + (long)(b * Nn + n) * (64 * TT);
    float* op = out + (long)(b * Nn + n) * (64 * TT);

    for (int tz = 0; tz < 2; tz++) {
        int toff = tz * 100;
        float acc1[16][4];
#pragma unroll
        for (int u = 0; u < 16; u++)
#pragma unroll
            for (int s = 0; s < 4; s++) acc1[u][s] = 0.0f;
#pragma unroll 4
        for (int j = 0; j < 64; j++) {
            float xr[4];
#pragma unroll
            for (int s = 0; s < 4; s++) {
                int t = tx + 32 * s;
                xr[s] = xp[j * TT + toff + (t < 100 ? t : 0)];
            }
#pragma unroll
            for (int u = 0; u < 16; u++) {
                float w = w1[j * 128 + ty + 8 * u];
#pragma unroll
                for (int s = 0; s < 4; s++) acc1[u][s] += w * xr[s];
            }
        }
        __syncthreads();
#pragma unroll
        for (int u = 0; u < 16; u++) {
            int o = ty + 8 * u;
            float bb = b1s[o];
#pragma unroll
            for (int s = 0; s < 4; s++) {
                int t = tx + 32 * s;
                if (t < 100) {
                    float v = acc1[u][s] + bb;
                    v = v > 0.0f ? v : expm1f(v);
                    hmS[o * 100 + t] = v;
                }
            }
        }
        __syncthreads();
        float acc2[8][4];
#pragma unroll
        for (int u = 0; u < 8; u++)
#pragma unroll
            for (int s = 0; s < 4; s++) acc2[u][s] = 0.0f;
#pragma unroll 4
        for (int j = 0; j < 128; j++) {
            float xr[4];
#pragma unroll
            for (int s = 0; s < 4; s++) {
                int t = tx + 32 * s;
                xr[s] = hmS[j * 100 + (t < 100 ? t : 0)];
            }
#pragma unroll
            for (int u = 0; u < 8; u++) {
                float w = w2[j * 64 + ty + 8 * u];
#pragma unroll
                for (int s = 0; s < 4; s++) acc2[u][s] += w * xr[s];
            }
        }
#pragma unroll
        for (int u = 0; u < 8; u++) {
            int o = ty + 8 * u;
            float bb = b2s[o];
#pragma unroll
            for (int s = 0; s < 4; s++) {
                int t = tx + 32 * s;
                if (t < 100) op[o * TT + toff + t] = tanhf(acc2[u][s] + bb);
            }
        }
        __syncthreads();
    }
}

// -------------------------------- launch ------------------------------------
#define GETSYM(var, sym)                                       \
    do {                                                       \
        void* _p = nullptr;                                    \
        cudaGetSymbolAddress(&_p, sym);                        \
        var = (decltype(var))_p;                               \
    } while (0)

extern "C" void kernel_launch(void* const* d_in, const int* in_sizes, int n_in,
                              void* d_out, int out_size) {
    (void)in_sizes; (void)n_in; (void)out_size;
    const float* x   = (const float*)d_in[0];
    const int*   ei0 = (const int*)d_in[1];
    const float* ea0 = (const float*)d_in[2];
    const int*   ei1 = (const int*)d_in[3];
    const float* ea1 = (const float*)d_in[4];
    const int*   ei2 = (const int*)d_in[5];
    const float* ea2 = (const float*)d_in[6];
    const float* A1  = (const float*)d_in[7];
    const float* Wk1 = (const float*)d_in[8];
    const float* Wr1 = (const float*)d_in[9];
    const float* b1  = (const float*)d_in[10];
    const float* A2  = (const float*)d_in[11];
    const float* Wk2 = (const float*)d_in[12];
    const float* Wr2 = (const float*)d_in[13];
    const float* b2  = (const float*)d_in[14];
    const float* A3  = (const float*)d_in[15];
    const float* Wk3 = (const float*)d_in[16];
    const float* Wr3 = (const float*)d_in[17];
    const float* b3  = (const float*)d_in[18];
    const float* P01 = (const float*)d_in[19];
    const float* P12 = (const float*)d_in[20];
    const float* P23 = (const float*)d_in[21];
    const float* f1w = (const float*)d_in[22];
    const float* f1b = (const float*)d_in[23];
    const float* f2w = (const float*)d_in[24];
    const float* f2b = (const float*)d_in[25];

    const int N0 = 2048, N1 = 512, N2 = 128, N3 = 64;

    float *p1, *p2, *p3;
    __nv_bfloat16 *A1h, *A1l, *A2h, *A2l, *A3h, *A3l, *Bh, *Bl;
    __nv_bfloat16 *Wt1h, *Wt1l, *Wt2h, *Wt2l;
    int *off0, *perm0, *off1, *perm1, *off2, *perm2;
    float *inv0, *inv1, *inv2;
    GETSYM(p1, g_p1); GETSYM(p2, g_p2); GETSYM(p3, g_p3);
    GETSYM(A1h, g_A1h); GETSYM(A1l, g_A1l);
    GETSYM(A2h, g_A2h); GETSYM(A2l, g_A2l);
    GETSYM(A3h, g_A3h); GETSYM(A3l, g_A3l);
    GETSYM(Bh, g_Bh); GETSYM(Bl, g_Bl);
    GETSYM(Wt1h, g_Wt1h); GETSYM(Wt1l, g_Wt1l);
    GETSYM(Wt2h, g_Wt2h); GETSYM(Wt2l, g_Wt2l);
    GETSYM(off0, g_off0); GETSYM(perm0, g_perm0);
    GETSYM(off1, g_off1); GETSYM(perm1, g_perm1);
    GETSYM(off2, g_off2); GETSYM(perm2, g_perm2);
    GETSYM(inv0, g_inv0); GETSYM(inv1, g_inv1); GETSYM(inv2, g_inv2);

    const int SMEM_GEMM = 98304;
    cudaFuncSetAttribute(mma_gemm_kernel, cudaFuncAttributeMaxDynamicSharedMemorySize,
                         SMEM_GEMM);
    // cat-only dynamic smem (Wt loaded from global): 2*K4*400 + COUT*4
    const int SMEM_F1 = 2 * 64 * 400 + 32 * 4;    // ~50.1KB -> 4 blocks/SM
    const int SMEM_F2 = 2 * 128 * 400 + 64 * 4;   // ~100.3KB -> 2 blocks/SM
    cudaFuncSetAttribute((const void*)gcnf_kernel<16, 32>,
                         cudaFuncAttributeMaxDynamicSharedMemorySize, SMEM_F1);
    cudaFuncSetAttribute((const void*)gcnf_kernel<32, 64>,
                         cudaFuncAttributeMaxDynamicSharedMemorySize, SMEM_F2);
    const int SMEM_HEAD = (8192 + 8192 + 128 + 64 + 12800) * 4;
    cudaFuncSetAttribute(head_kernel, cudaFuncAttributeMaxDynamicSharedMemorySize,
                         SMEM_HEAD);

    // ---- setup: CSR (3 blocks) + splitA + Wt, one launch ----
    const long SPLIT_TOT = 512L * 2048 + 128 * 512 + 128 * 128 + 32 * 64 + 2 * 64 * 64;
    setup_kernel<<<3 + (int)((SPLIT_TOT + 1023) / 1024), 1024>>>(
        ei0, ei1, ei2, off0, perm0, inv0, off1, perm1, inv1, off2, perm2, inv2,
        P01, P12, P23, A1h, A1l, A2h, A2l, A3h, A3l,
        Wk2, Wr2, Wk3, Wr3, Wt1h, Wt1l, Wt2h, Wt2l);

    // ---- level 0->1 GCN ----
    gcn1_kernel<<<N0, 256>>>(x, ea0, A1, Wk1, Wr1, b1, ei0, off0, perm0, inv0, Bh, Bl);

    // ---- pool1: M=512, K=2048, F=3200 ----
    mma_gemm_kernel<<<dim3(3200 / 64, 512 / 128, 2), 256, SMEM_GEMM>>>(
        A1h, A1l, Bh, Bl, p1, 512, 2048, 3200);

    // ---- level 1->2 GCN (scalar gather + tensor-core combine) ----
    gcnf_kernel<16, 32><<<dim3(N1, 2), 256, SMEM_F1>>>(
        p1, ea1, A2, Wt1h, Wt1l, b2, ei1, off1, perm1, inv1, Bh, Bl, N1);

    // ---- pool2: M=128, K=512, F=6400 ----
    mma_gemm_kernel<<<dim3(6400 / 64, 1, 2), 256, SMEM_GEMM>>>(
        A2h, A2l, Bh, Bl, p2, 128, 512, 6400);

    // ---- level 2->3 GCN ----
    gcnf_kernel<32, 64><<<dim3(N2, 2), 256, SMEM_F2>>>(
        p2, ea2, A3, Wt2h, Wt2l, b3, ei2, off2, perm2, inv2, Bh, Bl, N2);

    // ---- pool3: M=64 (padded 128), K=128, F=12800 ----
    mma_gemm_kernel<<<dim3(12800 / 64, 1, 2), 256, SMEM_GEMM>>>(
        A3h, A3l, Bh, Bl, p3, 64, 128, 12800);

    // ---- fused head ----
    head_kernel<<<dim3(N3, 2), 256, SMEM_HEAD>>>(
        p3, f1w, f1b, f2w, f2b, (float*)d_out, N3);
}

// round 16
// speedup vs baseline: 1.3013x; 1.0145x over previous
#include <cuda_runtime.h>
#include <cuda_bf16.h>
#include <cstdint>

// ============================================================================
// Graph_ODE_RNN — 8-launch pipeline (R15 + M64 GEMM for pool3 + LDM4T combine):
//  [csr+splitA+Wt] -> gcn1 -> pool1 -> gcnf1 -> pool2 -> gcnf2 -> pool3 -> head
// ============================================================================

#define TT 200

// ---------------- static scratch (no allocation allowed) -------------------
__device__ float g_p1[2 * 512 * 16 * TT];
__device__ float g_p2[2 * 128 * 32 * TT];
__device__ float g_p3[2 * 64 * 64 * TT];

__device__ __nv_bfloat16 g_A1h[512 * 2048], g_A1l[512 * 2048];
__device__ __nv_bfloat16 g_A2h[128 * 512],  g_A2l[128 * 512];
__device__ __nv_bfloat16 g_A3h[128 * 128],  g_A3l[128 * 128];  // M padded 64->128
__device__ __nv_bfloat16 g_Bh[2 * 2048 * 3200], g_Bl[2 * 2048 * 3200];

// combine weights W^T, bf16 hi/lo, chunk layout [kc][m][64]
__device__ __nv_bfloat16 g_Wt1h[32 * 64],  g_Wt1l[32 * 64];
__device__ __nv_bfloat16 g_Wt2h[2 * 64 * 64], g_Wt2l[2 * 64 * 64];

__device__ int g_off0[2049], g_perm0[16384];
__device__ int g_off1[513],  g_perm1[8192];
__device__ int g_off2[129],  g_perm2[2048];
__device__ float g_inv0[2048], g_inv1[512], g_inv2[128];

// ---------------------------- helpers ---------------------------------------
__device__ __forceinline__ uint32_t smem_u32(const void* p) {
    uint32_t a;
    asm("{ .reg .u64 t; cvta.to.shared.u64 t, %1; cvt.u32.u64 %0, t; }"
        : "=r"(a) : "l"(p));
    return a;
}

#define SW128(x) ((x) ^ (((x) >> 3) & 0x70))

#define LDM4(r, addr)                                                            \
    asm volatile("ldmatrix.sync.aligned.m8n8.x4.shared.b16 {%0,%1,%2,%3}, [%4];" \
                 : "=r"((r)[0]), "=r"((r)[1]), "=r"((r)[2]), "=r"((r)[3])        \
                 : "r"(addr))

#define LDM2T(r, addr)                                                           \
    asm volatile("ldmatrix.sync.aligned.m8n8.x2.trans.shared.b16 {%0,%1}, [%2];" \
                 : "=r"((r)[0]), "=r"((r)[1]) : "r"(addr))

#define LDM4T(r, addr)                                                           \
    asm volatile("ldmatrix.sync.aligned.m8n8.x4.trans.shared.b16 "               \
                 "{%0,%1,%2,%3}, [%4];"                                          \
                 : "=r"((r)[0]), "=r"((r)[1]), "=r"((r)[2]), "=r"((r)[3])        \
                 : "r"(addr))

#define MMA_BF16(c, a, bb)                                                       \
    asm volatile("mma.sync.aligned.m16n8k16.row.col.f32.bf16.bf16.f32 "          \
                 "{%0,%1,%2,%3}, {%4,%5,%6,%7}, {%8,%9}, {%0,%1,%2,%3};"         \
                 : "+f"((c)[0]), "+f"((c)[1]), "+f"((c)[2]), "+f"((c)[3])        \
                 : "r"((a)[0]), "r"((a)[1]), "r"((a)[2]), "r"((a)[3]),           \
                   "r"((bb)[0]), "r"((bb)[1]))

#define CP16(dst, src)                                                           \
    asm volatile("cp.async.cg.shared.global [%0], [%1], 16;" :: "r"(dst), "l"(src))
#define CP_COMMIT asm volatile("cp.async.commit_group;" ::: "memory")
#define CP_WAIT0  asm volatile("cp.async.wait_group 0;" ::: "memory")

__device__ __forceinline__ uint32_t pack_bf2(float a, float b) {
    __nv_bfloat16 ha = __float2bfloat16(a), hb = __float2bfloat16(b);
    return (uint32_t)__bfloat16_as_ushort(ha) |
           ((uint32_t)__bfloat16_as_ushort(hb) << 16);
}

// -------------- merged setup: 3 CSR blocks + split/Wt blocks ----------------
__global__ __launch_bounds__(1024)
void setup_kernel(const int* e0, const int* e1, const int* e2,
                  int* o0, int* p0, float* v0,
                  int* o1, int* p1, float* v1,
                  int* o2, int* p2, float* v2,
                  const float* __restrict__ P01, const float* __restrict__ P12,
                  const float* __restrict__ P23,
                  __nv_bfloat16* A1h, __nv_bfloat16* A1l,
                  __nv_bfloat16* A2h, __nv_bfloat16* A2l,
                  __nv_bfloat16* A3h, __nv_bfloat16* A3l,
                  const float* __restrict__ Wk2, const float* __restrict__ Wr2,
                  const float* __restrict__ Wk3, const float* __restrict__ Wr3,
                  __nv_bfloat16* Wt1h, __nv_bfloat16* Wt1l,
                  __nv_bfloat16* Wt2h, __nv_bfloat16* Wt2l) {
    int tid = threadIdx.x;
    if (blockIdx.x >= 3) {
        const long S1 = 512 * 2048, S2 = 128 * 512, S3 = 128 * 128;
        const long W1 = 32 * 64, W2 = 2 * 64 * 64;
        long i = (long)(blockIdx.x - 3) * 1024 + tid;
        float v; __nv_bfloat16 *H, *L; long o;
        if (i < S1) { o = i; v = P01[o]; H = A1h; L = A1l; }
        else if (i < S1 + S2) { o = i - S1; v = P12[o]; H = A2h; L = A2l; }
        else if (i < S1 + S2 + S3) {
            o = i - S1 - S2;
            v = ((o >> 7) < 64) ? P23[o] : 0.0f;
            H = A3h; L = A3l;
        } else if (i < S1 + S2 + S3 + W1) {
            o = i - S1 - S2 - S3;
            int m = (int)(o >> 6), kk = (int)(o & 63);
            v = (kk < 48) ? Wk2[kk * 32 + m] : Wr2[(kk - 48) * 32 + m];
            H = Wt1h; L = Wt1l;
        } else if (i < S1 + S2 + S3 + W1 + W2) {
            o = i - S1 - S2 - S3 - W1;
            int kc = (int)(o >> 12), rem = (int)(o & 4095);
            int m = rem >> 6, kk = rem & 63;
            int j = kc * 64 + kk;
            v = (j < 96) ? Wk3[j * 64 + m] : Wr3[(j - 96) * 64 + m];
            H = Wt2h; L = Wt2l;
        } else return;
        __nv_bfloat16 hi = __float2bfloat16(v);
        H[o] = hi;
        L[o] = __float2bfloat16(v - __bfloat162float(hi));
        return;
    }
    // ---- CSR part: one block per level ----
    __shared__ int sa[2048];
    __shared__ int sb[2048];
    __shared__ int scur[2048];
    int lvl = blockIdx.x;
    const int* dst = lvl == 0 ? e0 + 16384 : (lvl == 1 ? e1 + 8192 : e2 + 2048);
    int E = lvl == 0 ? 16384 : (lvl == 1 ? 8192 : 2048);
    int N = lvl == 0 ? 2048 : (lvl == 1 ? 512 : 128);
    int* off = lvl == 0 ? o0 : (lvl == 1 ? o1 : o2);
    int* perm = lvl == 0 ? p0 : (lvl == 1 ? p1 : p2);
    float* inv = lvl == 0 ? v0 : (lvl == 1 ? v1 : v2);

    for (int q = tid; q < 2048; q += 1024) sa[q] = 0;
    __syncthreads();
    for (int i = tid; i < E; i += 1024) atomicAdd(&sa[dst[i]], 1);
    __syncthreads();
    for (int q = tid; q < 2048; q += 1024) {
        int dg = sa[q];
        sb[q] = dg;
        if (q < N) inv[q] = 1.0f / (float)(dg > 0 ? dg : 1);
    }
    __syncthreads();
    int* pc = sa;
    int* pn = scur;
    for (int d = 1; d < 2048; d <<= 1) {
        for (int q = tid; q < 2048; q += 1024) {
            int v = pc[q];
            if (q >= d) v += pc[q - d];
            pn[q] = v;
        }
        __syncthreads();
        int* t = pc; pc = pn; pn = t;
    }
    for (int q = tid; q < N; q += 1024) {
        int o = (q == 0) ? 0 : pc[q - 1];
        off[q] = o;
        pn[q] = o;
    }
    if (tid == 0) off[N] = pc[N - 1];
    __syncthreads();
    for (int i = tid; i < E; i += 1024) {
        int p = atomicAdd(&pn[dst[i]], 1);
        perm[p] = i;
    }
    __syncthreads();
    for (int n = tid; n < N; n += 1024) {
        int a = (n == 0) ? 0 : pc[n - 1];
        int b = pc[n];
        for (int k = a + 1; k < b; k++) {
            int v = perm[k];
            int j = k - 1;
            while (j >= a && perm[j] > v) { perm[j + 1] = perm[j]; j--; }
            perm[j + 1] = v;
        }
    }
}

// ------- level-1 GCN (both batches per block, staged edge weights) ----------
__global__ __launch_bounds__(256)
void gcn1_kernel(const float* __restrict__ x, const float* __restrict__ ea,
                 const float* __restrict__ Amat,
                 const float* __restrict__ Wk, const float* __restrict__ Wr,
                 const float* __restrict__ bias,
                 const int* __restrict__ srcArr, const int* __restrict__ off,
                 const int* __restrict__ perm, const float* __restrict__ inv_cnt,
                 __nv_bfloat16* __restrict__ Bh, __nv_bfloat16* __restrict__ Bl) {
    __shared__ float sA[9];
    __shared__ float sW[80];
    __shared__ int sSrc[64];
    __shared__ float sEw[64 * 3];
    const int N0 = 2048;
    int n = blockIdx.x;
    int t = threadIdx.x;
    if (t < 9) sA[t] = Amat[t];
    if (t < 48) sW[t] = Wk[t];
    else if (t < 64) sW[t] = Wr[t - 48];
    else if (t < 80) sW[t] = bias[t - 64];
    __syncthreads();

    float a0[3] = {0.f, 0.f, 0.f};
    float a1[3] = {0.f, 0.f, 0.f};
    int e0 = off[n], e1 = off[n + 1];
    for (int base = e0; base < e1; base += 64) {
        int cnt = min(64, e1 - base);
        __syncthreads();
        if (t < cnt) {
            int e = perm[base + t];
            sSrc[t] = srcArr[e];
            float u0 = ea[e * 3 + 0], u1 = ea[e * 3 + 1], u2 = ea[e * 3 + 2];
            float w0 = u0 * sA[0] + u1 * sA[3] + u2 * sA[6];
            float w1 = u0 * sA[1] + u1 * sA[4] + u2 * sA[7];
            float w2 = u0 * sA[2] + u1 * sA[5] + u2 * sA[8];
            float m = fmaxf(w0, fmaxf(w1, w2));
            float q0 = __expf(w0 - m), q1 = __expf(w1 - m), q2 = __expf(w2 - m);
            float qi = 1.0f / (q0 + q1 + q2);
            sEw[t * 3 + 0] = q0 * qi;
            sEw[t * 3 + 1] = q1 * qi;
            sEw[t * 3 + 2] = q2 * qi;
        }
        __syncthreads();
        if (t < TT) {
#pragma unroll 2
            for (int j = 0; j < cnt; j++) {
                int src = sSrc[j];
                float w0 = sEw[j * 3 + 0], w1 = sEw[j * 3 + 1], w2 = sEw[j * 3 + 2];
                float va = x[src * TT + t];
                float vb = x[(N0 + src) * TT + t];
                a0[0] += w0 * va; a0[1] += w1 * va; a0[2] += w2 * va;
                a1[0] += w0 * vb; a1[1] += w1 * vb; a1[2] += w2 * vb;
            }
        }
    }
    if (t >= TT) return;
    float inv = inv_cnt[n];
#pragma unroll
    for (int k = 0; k < 3; k++) { a0[k] *= inv; a1[k] *= inv; }
    float xo0 = x[n * TT + t];
    float xo1 = x[(N0 + n) * TT + t];
    long base0 = ((long)n * 16) * TT + t;
    long base1 = ((long)(N0 + n) * 16) * TT + t;
#pragma unroll
    for (int o = 0; o < 16; o++) {
        float v = a0[0] * sW[o] + a0[1] * sW[16 + o] + a0[2] * sW[32 + o] +
                  xo0 * sW[48 + o] + sW[64 + o];
        v = v > 0.0f ? v : expm1f(v);
        __nv_bfloat16 hi = __float2bfloat16(v);
        Bh[base0 + (long)o * TT] = hi;
        Bl[base0 + (long)o * TT] = __float2bfloat16(v - __bfloat162float(hi));
        v = a1[0] * sW[o] + a1[1] * sW[16 + o] + a1[2] * sW[32 + o] +
            xo1 * sW[48 + o] + sW[64 + o];
        v = v > 0.0f ? v : expm1f(v);
        hi = __float2bfloat16(v);
        Bh[base1 + (long)o * TT] = hi;
        Bl[base1 + (long)o * TT] = __float2bfloat16(v - __bfloat162float(hi));
    }
}

// ----- fused GCN level: scalar gather + tensor-core combine -----------------
// Combine A-fragments loaded directly from global Wt (no smem staging);
// B-fragments via x4 trans-ldmatrix (2 kq chunks per instruction).
// dyn smem: [0, K4*400) chi | [K4*400, 2*K4*400) clo | sbias
template <int CIN, int COUT>
__global__ __launch_bounds__(256)
void gcnf_kernel(const float* __restrict__ xin, const float* __restrict__ ea,
                 const float* __restrict__ Amat,
                 const __nv_bfloat16* __restrict__ Wth,
                 const __nv_bfloat16* __restrict__ Wtl,
                 const float* __restrict__ bias,
                 const int* __restrict__ srcArr, const int* __restrict__ off,
                 const int* __restrict__ perm, const float* __restrict__ inv_cnt,
                 __nv_bfloat16* __restrict__ Bh, __nv_bfloat16* __restrict__ Bl, int Nn) {
    constexpr int K4 = 4 * CIN;
    constexpr int MT = COUT / 16;
    constexpr int KQ = K4 / 16;
    extern __shared__ __align__(16) char dsm[];
    const uint32_t chi_o = 0;
    const uint32_t clo_o = K4 * 400;
    float* sbias = (float*)(dsm + 2 * K4 * 400);
    uint32_t sb = smem_u32(dsm);
    __shared__ float sA[9];
    __shared__ int sSrc[64];
    __shared__ float sEw[64 * 3];

    int n = blockIdx.x, b = blockIdx.y;
    int tid = threadIdx.x, lane = tid & 31, w = tid >> 5;
    int tx = lane, ty = w;
    if (tid < 9) sA[tid] = Amat[tid];
    if (tid < COUT) sbias[tid] = bias[tid];
    __syncthreads();

    // ---- gather (scalar form): acc[k][u][s], (ch = ty+8u, t = tx+32s) ----
    constexpr int U = CIN / 8;
    float acc[3][U][7];
#pragma unroll
    for (int k = 0; k < 3; k++)
#pragma unroll
        for (int u = 0; u < U; u++)
#pragma unroll
            for (int s = 0; s < 7; s++) acc[k][u][s] = 0.0f;

    int e0 = off[n], e1 = off[n + 1];
    for (int base = e0; base < e1; base += 64) {
        int cnt = min(64, e1 - base);
        __syncthreads();
        if (tid < cnt) {
            int e = perm[base + tid];
            sSrc[tid] = srcArr[e];
            float u0 = ea[e * 3 + 0], u1 = ea[e * 3 + 1], u2 = ea[e * 3 + 2];
            float w0 = u0 * sA[0] + u1 * sA[3] + u2 * sA[6];
            float w1 = u0 * sA[1] + u1 * sA[4] + u2 * sA[7];
            float w2 = u0 * sA[2] + u1 * sA[5] + u2 * sA[8];
            float m = fmaxf(w0, fmaxf(w1, w2));
            float q0 = __expf(w0 - m), q1 = __expf(w1 - m), q2 = __expf(w2 - m);
            float qi = 1.0f / (q0 + q1 + q2);
            sEw[tid * 3 + 0] = q0 * qi;
            sEw[tid * 3 + 1] = q1 * qi;
            sEw[tid * 3 + 2] = q2 * qi;
        }
        __syncthreads();
        for (int j = 0; j < cnt; j++) {
            float q0 = sEw[j * 3 + 0], q1 = sEw[j * 3 + 1], q2 = sEw[j * 3 + 2];
            const float* xp = xin + (long)(b * Nn + sSrc[j]) * (CIN * TT);
#pragma unroll
            for (int u = 0; u < U; u++) {
#pragma unroll
                for (int s = 0; s < 7; s++) {
                    int t = tx + 32 * s;
                    float v = xp[(ty + 8 * u) * TT + (t < TT ? t : 0)];
                    acc[0][u][s] += q0 * v;
                    acc[1][u][s] += q1 * v;
                    acc[2][u][s] += q2 * v;
                }
            }
        }
    }

    // ---- build cat = [G | x] in bf16 hi/lo smem ----
    float inv = inv_cnt[n];
    __syncthreads();
    __nv_bfloat16* chi = (__nv_bfloat16*)(dsm + chi_o);
    __nv_bfloat16* clo = (__nv_bfloat16*)(dsm + clo_o);
#pragma unroll
    for (int k = 0; k < 3; k++)
#pragma unroll
        for (int u = 0; u < U; u++)
#pragma unroll
            for (int s = 0; s < 7; s++) {
                int t = tx + 32 * s;
                if (t < TT) {
                    int row = k * CIN + ty + 8 * u;
                    float v = acc[k][u][s] * inv;
                    __nv_bfloat16 hi = __float2bfloat16(v);
                    chi[row * TT + t] = hi;
                    clo[row * TT + t] = __float2bfloat16(v - __bfloat162float(hi));
                }
            }
    {
        const float* xp = xin + (long)(b * Nn + n) * (CIN * TT);
#pragma unroll
        for (int u = 0; u < U; u++)
#pragma unroll
            for (int s = 0; s < 7; s++) {
                int t = tx + 32 * s;
                if (t < TT) {
                    int c = ty + 8 * u;
                    float v = xp[c * TT + t];
                    int row = 3 * CIN + c;
                    __nv_bfloat16 hi = __float2bfloat16(v);
                    chi[row * TT + t] = hi;
                    clo[row * TT + t] = __float2bfloat16(v - __bfloat162float(hi));
                }
            }
    }
    __syncthreads();

    // ---- combine on tensor cores: out[COUT x 200] = Wt @ cat, bf16x3 ----
    int mt = w % MT;
    int ntStart = w / MT;
    constexpr int NTSTRIDE = 8 / MT;

    uint32_t ah[KQ][4], al[KQ][4];
    {
        int m0 = mt * 16 + (lane >> 2);
        int kk0 = (lane & 3) * 2;
#pragma unroll
        for (int kq = 0; kq < KQ; kq++) {
            int kc = kq >> 2;
            int kkb = (kq & 3) * 16 + kk0;
            const __nv_bfloat16* bhp = Wth + kc * COUT * 64;
            const __nv_bfloat16* blp = Wtl + kc * COUT * 64;
            ah[kq][0] = *(const uint32_t*)&bhp[m0 * 64 + kkb];
            ah[kq][1] = *(const uint32_t*)&bhp[(m0 + 8) * 64 + kkb];
            ah[kq][2] = *(const uint32_t*)&bhp[m0 * 64 + kkb + 8];
            ah[kq][3] = *(const uint32_t*)&bhp[(m0 + 8) * 64 + kkb + 8];
            al[kq][0] = *(const uint32_t*)&blp[m0 * 64 + kkb];
            al[kq][1] = *(const uint32_t*)&blp[(m0 + 8) * 64 + kkb];
            al[kq][2] = *(const uint32_t*)&blp[m0 * 64 + kkb + 8];
            al[kq][3] = *(const uint32_t*)&blp[(m0 + 8) * 64 + kkb + 8];
        }
    }

    long obase = (long)(b * Nn + n) * (COUT * TT);
    int o0 = mt * 16 + (lane >> 2);
    float bb0 = sbias[o0], bb1 = sbias[o0 + 8];
    for (int nt = ntStart; nt < 25; nt += NTSTRIDE) {
        float c[4] = {0.f, 0.f, 0.f, 0.f};
#pragma unroll
        for (int kp = 0; kp < KQ / 2; kp++) {
            // x4 trans: rows kp*32 .. kp*32+31 -> fragments for kq=2kp, 2kp+1
            uint32_t offB = (uint32_t)(kp * 32 + lane) * 400 + nt * 16;
            uint32_t bh4[4], bl4[4];
            LDM4T(bh4, sb + chi_o + offB);
            LDM4T(bl4, sb + clo_o + offB);
            MMA_BF16(c, ah[2 * kp], bh4);
            MMA_BF16(c, ah[2 * kp], bl4);
            MMA_BF16(c, al[2 * kp], bh4);
            MMA_BF16(c, ah[2 * kp + 1], bh4 + 2);
            MMA_BF16(c, ah[2 * kp + 1], bl4 + 2);
            MMA_BF16(c, al[2 * kp + 1], bh4 + 2);
        }
        int t0 = nt * 8 + (lane & 3) * 2;
        float v0 = c[0] + bb0; v0 = v0 > 0.f ? v0 : expm1f(v0);
        float v1 = c[1] + bb0; v1 = v1 > 0.f ? v1 : expm1f(v1);
        __nv_bfloat16 h0 = __float2bfloat16(v0), h1 = __float2bfloat16(v1);
        *(uint32_t*)&Bh[obase + (long)o0 * TT + t0] =
            (uint32_t)__bfloat16_as_ushort(h0) | ((uint32_t)__bfloat16_as_ushort(h1) << 16);
        *(uint32_t*)&Bl[obase + (long)o0 * TT + t0] =
            pack_bf2(v0 - __bfloat162float(h0), v1 - __bfloat162float(h1));
        float v2 = c[2] + bb1; v2 = v2 > 0.f ? v2 : expm1f(v2);
        float v3 = c[3] + bb1; v3 = v3 > 0.f ? v3 : expm1f(v3);
        __nv_bfloat16 h2 = __float2bfloat16(v2), h3 = __float2bfloat16(v3);
        *(uint32_t*)&Bh[obase + (long)(o0 + 8) * TT + t0] =
            (uint32_t)__bfloat16_as_ushort(h2) | ((uint32_t)__bfloat16_as_ushort(h3) << 16);
        *(uint32_t*)&Bl[obase + (long)(o0 + 8) * TT + t0] =
            pack_bf2(v2 - __bfloat162float(h2), v3 - __bfloat162float(h3));
    }
}

// ------- bf16x3 GEMM (R8): Kc=64, 96KB, cp.async double-buffered -------------
__global__ __launch_bounds__(256)
void mma_gemm_kernel(const __nv_bfloat16* __restrict__ Ahi, const __nv_bfloat16* __restrict__ Alo,
                     const __nv_bfloat16* __restrict__ Bhi, const __nv_bfloat16* __restrict__ Blo,
                     float* __restrict__ C, int Mout, int K, int F) {
    extern __shared__ __align__(16) char smem[];
    const int BUF = 49152;
    const int OFF_AH = 0, OFF_AL = 16384, OFF_BH = 32768, OFF_BL = 40960;
    uint32_t sbase = smem_u32(smem);
    int tid = threadIdx.x, lane = tid & 31, w = tid >> 5;
    int mw = w & 1, fw = w >> 1;
    int f0 = blockIdx.x * 64, row0 = blockIdx.y * 128, b = blockIdx.z;

    const __nv_bfloat16* BhB = Bhi + (long)b * K * F;
    const __nv_bfloat16* BlB = Blo + (long)b * K * F;

    float acc[4][2][4];
#pragma unroll
    for (int mt = 0; mt < 4; mt++)
#pragma unroll
        for (int nt = 0; nt < 2; nt++)
#pragma unroll
            for (int q = 0; q < 4; q++) acc[mt][nt][q] = 0.0f;

    int r = tid >> 3, cb = (tid & 7) * 16;
    int nchunk = K >> 6;

#define STAGE(bo, k0)                                                              \
    do {                                                                           \
        _Pragma("unroll")                                                          \
        for (int i = 0; i < 4; i++) {                                              \
            int rr = r + i * 32;                                                   \
            uint32_t so = SW128(rr * 128 + cb);                                    \
            CP16(sbase + (bo) + OFF_AH + so,                                       \
                 (const char*)&Ahi[(long)(row0 + rr) * K + (k0) + (cb >> 1)]);     \
            CP16(sbase + (bo) + OFF_AL + so,                                       \
                 (const char*)&Alo[(long)(row0 + rr) * K + (k0) + (cb >> 1)]);     \
        }                                                                          \
        _Pragma("unroll")                                                          \
        for (int i = 0; i < 2; i++) {                                              \
            int rr = r + i * 32;                                                   \
            uint32_t so = SW128(rr * 128 + cb);                                    \
            long gi = (long)((k0) + rr) * F + f0 + (cb >> 1);                      \
            CP16(sbase + (bo) + OFF_BH + so, (const char*)&BhB[gi]);               \
            CP16(sbase + (bo) + OFF_BL + so, (const char*)&BlB[gi]);               \
        }                                                                          \
    } while (0)

    STAGE(0, 0);
    CP_COMMIT;

    int buf = 0;
    for (int kc = 0; kc < nchunk; kc++) {
        CP_WAIT0;
        __syncthreads();
        if (kc + 1 < nchunk) {
            STAGE((buf ^ 1) * BUF, (kc + 1) << 6);
            CP_COMMIT;
        }
        int bo = buf * BUF;
#pragma unroll
        for (int ks = 0; ks < 4; ks++) {
            uint32_t ah[4][4], al[4][4], bh[2][2], bl[2][2];
#pragma unroll
            for (int mt = 0; mt < 4; mt++) {
                uint32_t off = SW128((mw * 64 + mt * 16 + (lane & 15)) * 128 +
                                     ks * 32 + (lane >> 4) * 16);
                LDM4(ah[mt], sbase + bo + OFF_AH + off);
                LDM4(al[mt], sbase + bo + OFF_AL + off);
            }
#pragma unroll
            for (int nt = 0; nt < 2; nt++) {
                uint32_t off = SW128((ks * 16 + (lane & 15)) * 128 + fw * 32 + nt * 16);
                LDM2T(bh[nt], sbase + bo + OFF_BH + off);
                LDM2T(bl[nt], sbase + bo + OFF_BL + off);
            }
#pragma unroll
            for (int mt = 0; mt < 4; mt++) {
#pragma unroll
                for (int nt = 0; nt < 2; nt++) {
                    MMA_BF16(acc[mt][nt], ah[mt], bh[nt]);
                    MMA_BF16(acc[mt][nt], ah[mt], bl[nt]);
                    MMA_BF16(acc[mt][nt], al[mt], bh[nt]);
                }
            }
        }
        __syncthreads();
        buf ^= 1;
    }
#undef STAGE

#pragma unroll
    for (int mt = 0; mt < 4; mt++) {
        int gr = row0 + mw * 64 + mt * 16 + (lane >> 2);
#pragma unroll
        for (int nt = 0; nt < 2; nt++) {
            int gc = f0 + fw * 16 + nt * 8 + (lane & 3) * 2;
            if (gr < Mout)
                *(float2*)&C[((long)b * Mout + gr) * F + gc] =
                    make_float2(acc[mt][nt][0], acc[mt][nt][1]);
            if (gr + 8 < Mout)
                *(float2*)&C[((long)b * Mout + gr + 8) * F + gc] =
                    make_float2(acc[mt][nt][2], acc[mt][nt][3]);
        }
    }
}

// ------- bf16x3 GEMM, M=64 tile (pool3): 64KB smem, 3 blocks/SM --------------
// Block: 64(M) x 64(F); 8 warps = 4 m-tiles x 2 f-halves; Kc=64.
__global__ __launch_bounds__(256)
void mma_gemm64_kernel(const __nv_bfloat16* __restrict__ Ahi,
                       const __nv_bfloat16* __restrict__ Alo,
                       const __nv_bfloat16* __restrict__ Bhi,
                       const __nv_bfloat16* __restrict__ Blo,
                       float* __restrict__ C, int K, int F) {
    extern __shared__ __align__(16) char smem[];
    const int BUF = 32768;
    const int OFF_AH = 0, OFF_AL = 8192, OFF_BH = 16384, OFF_BL = 24576;
    uint32_t sbase = smem_u32(smem);
    int tid = threadIdx.x, lane = tid & 31, w = tid >> 5;
    int mt = w & 3, fh = w >> 2;
    int f0 = blockIdx.x * 64, b = blockIdx.z;

    const __nv_bfloat16* BhB = Bhi + (long)b * K * F;
    const __nv_bfloat16* BlB = Blo + (long)b * K * F;

    float acc[4][4];
#pragma unroll
    for (int nt = 0; nt < 4; nt++)
#pragma unroll
        for (int q = 0; q < 4; q++) acc[nt][q] = 0.0f;

    int r = tid >> 3, cb = (tid & 7) * 16;
    int nchunk = K >> 6;

#define STAGE64(bo, k0)                                                            \
    do {                                                                           \
        _Pragma("unroll")                                                          \
        for (int i = 0; i < 2; i++) {                                              \
            int rr = r + i * 32;                                                   \
            uint32_t so = SW128(rr * 128 + cb);                                    \
            CP16(sbase + (bo) + OFF_AH + so,                                       \
                 (const char*)&Ahi[(long)rr * K + (k0) + (cb >> 1)]);              \
            CP16(sbase + (bo) + OFF_AL + so,                                       \
                 (const char*)&Alo[(long)rr * K + (k0) + (cb >> 1)]);              \
            long gi = (long)((k0) + rr) * F + f0 + (cb >> 1);                      \
            CP16(sbase + (bo) + OFF_BH + so, (const char*)&BhB[gi]);               \
            CP16(sbase + (bo) + OFF_BL + so, (const char*)&BlB[gi]);               \
        }                                                                          \
    } while (0)

    STAGE64(0, 0);
    CP_COMMIT;

    int buf = 0;
    for (int kc = 0; kc < nchunk; kc++) {
        CP_WAIT0;
        __syncthreads();
        if (kc + 1 < nchunk) {
            STAGE64((buf ^ 1) * BUF, (kc + 1) << 6);
            CP_COMMIT;
        }
        int bo = buf * BUF;
#pragma unroll
        for (int ks = 0; ks < 4; ks++) {
            uint32_t ah[4], al[4], bh[4][2], bl[4][2];
            {
                uint32_t off = SW128((mt * 16 + (lane & 15)) * 128 +
                                     ks * 32 + (lane >> 4) * 16);
                LDM4(ah, sbase + bo + OFF_AH + off);
                LDM4(al, sbase + bo + OFF_AL + off);
            }
#pragma unroll
            for (int ntp = 0; ntp < 2; ntp++) {
                uint32_t off = SW128((ks * 16 + (lane & 15)) * 128 + fh * 64 + ntp * 32);
                // two 16B column groups -> fragments nt = ntp*2 and ntp*2+1
                LDM2T(bh[ntp * 2], sbase + bo + OFF_BH + off);
                LDM2T(bl[ntp * 2], sbase + bo + OFF_BL + off);
                uint32_t off2 = SW128((ks * 16 + (lane & 15)) * 128 + fh * 64 + ntp * 32 + 16);
                LDM2T(bh[ntp * 2 + 1], sbase + bo + OFF_BH + off2);
                LDM2T(bl[ntp * 2 + 1], sbase + bo + OFF_BL + off2);
            }
#pragma unroll
            for (int nt = 0; nt < 4; nt++) {
                MMA_BF16(acc[nt], ah, bh[nt]);
                MMA_BF16(acc[nt], ah, bl[nt]);
                MMA_BF16(acc[nt], al, bh[nt]);
            }
        }
        __syncthreads();
        buf ^= 1;
    }
#undef STAGE64

    int gr = mt * 16 + (lane >> 2);
#pragma unroll
    for (int nt = 0; nt < 4; nt++) {
        int gc = f0 + fh * 32 + nt * 8 + (lane & 3) * 2;
        *(float2*)&C[((long)b * 64 + gr) * F + gc] = make_float2(acc[nt][0], acc[nt][1]);
        *(float2*)&C[((long)b * 64 + gr + 8) * F + gc] = make_float2(acc[nt][2], acc[nt][3]);
    }
}

// ------------ fused head: elu(p3@W1+b1) -> tanh(.@W2+b2), smem hm -----------
__global__ __launch_bounds__(256)
void head_kernel(const float* __restrict__ p3,
                 const float* __restrict__ f1w, const float* __restrict__ f1b,
                 const float* __restrict__ f2w, const float* __restrict__ f2b,
                 float* __restrict__ out, int Nn) {
    extern __shared__ __align__(16) float ds[];
    float* w1 = ds;
    float* w2 = w1 + 8192;
    float* b1s = w2 + 8192;
    float* b2s = b1s + 128;
    float* hmS = b2s + 64;
    int n = blockIdx.x, b = blockIdx.y;
    int tid = threadIdx.x, tx = tid & 31, ty = tid >> 5;
    for (int q = tid; q < 8192; q += 256) { w1[q] = f1w[q]; w2[q] = f2w[q]; }
    if (tid < 128) b1s[tid] = f1b[tid];
    if (tid < 64) b2s[tid] = f2b[tid];
    __syncthreads();

    const float* xp = p3 + (long)(b * Nn + n) * (64 * TT);
    float* op = out + (long)(b * Nn + n) * (64 * TT);

    for (int tz = 0; tz < 2; tz++) {
        int toff = tz * 100;
        float acc1[16][4];
#pragma unroll
        for (int u = 0; u < 16; u++)
#pragma unroll
            for (int s = 0; s < 4; s++) acc1[u][s] = 0.0f;
#pragma unroll 4
        for (int j = 0; j < 64; j++) {
            float xr[4];
#pragma unroll
            for (int s = 0; s < 4; s++) {
                int t = tx + 32 * s;
                xr[s] = xp[j * TT + toff + (t < 100 ? t : 0)];
            }
#pragma unroll
            for (int u = 0; u < 16; u++) {
                float w = w1[j * 128 + ty + 8 * u];
#pragma unroll
                for (int s = 0; s < 4; s++) acc1[u][s] += w * xr[s];
            }
        }
        __syncthreads();
#pragma unroll
        for (int u = 0; u < 16; u++) {
            int o = ty + 8 * u;
            float bb = b1s[o];
#pragma unroll
            for (int s = 0; s < 4; s++) {
                int t = tx + 32 * s;
                if (t < 100) {
                    float v = acc1[u][s] + bb;
                    v = v > 0.0f ? v : expm1f(v);
                    hmS[o * 100 + t] = v;
                }
            }
        }
        __syncthreads();
        float acc2[8][4];
#pragma unroll
        for (int u = 0; u < 8; u++)
#pragma unroll
            for (int s = 0; s < 4; s++) acc2[u][s] = 0.0f;
#pragma unroll 4
        for (int j = 0; j < 128; j++) {
            float xr[4];
#pragma unroll
            for (int s = 0; s < 4; s++) {
                int t = tx + 32 * s;
                xr[s] = hmS[j * 100 + (t < 100 ? t : 0)];
            }
#pragma unroll
            for (int u = 0; u < 8; u++) {
                float w = w2[j * 64 + ty + 8 * u];
#pragma unroll
                for (int s = 0; s < 4; s++) acc2[u][s] += w * xr[s];
            }
        }
#pragma unroll
        for (int u = 0; u < 8; u++) {
            int o = ty + 8 * u;
            float bb = b2s[o];
#pragma unroll
            for (int s = 0; s < 4; s++) {
                int t = tx + 32 * s;
                if (t < 100) op[o * TT + toff + t] = tanhf(acc2[u][s] + bb);
            }
        }
        __syncthreads();
    }
}

// -------------------------------- launch ------------------------------------
#define GETSYM(var, sym)                                       \
    do {                                                       \
        void* _p = nullptr;                                    \
        cudaGetSymbolAddress(&_p, sym);                        \
        var = (decltype(var))_p;                               \
    } while (0)

extern "C" void kernel_launch(void* const* d_in, const int* in_sizes, int n_in,
                              void* d_out, int out_size) {
    (void)in_sizes; (void)n_in; (void)out_size;
    const float* x   = (const float*)d_in[0];
    const int*   ei0 = (const int*)d_in[1];
    const float* ea0 = (const float*)d_in[2];
    const int*   ei1 = (const int*)d_in[3];
    const float* ea1 = (const float*)d_in[4];
    const int*   ei2 = (const int*)d_in[5];
    const float* ea2 = (const float*)d_in[6];
    const float* A1  = (const float*)d_in[7];
    const float* Wk1 = (const float*)d_in[8];
    const float* Wr1 = (const float*)d_in[9];
    const float* b1  = (const float*)d_in[10];
    const float* A2  = (const float*)d_in[11];
    const float* Wk2 = (const float*)d_in[12];
    const float* Wr2 = (const float*)d_in[13];
    const float* b2  = (const float*)d_in[14];
    const float* A3  = (const float*)d_in[15];
    const float* Wk3 = (const float*)d_in[16];
    const float* Wr3 = (const float*)d_in[17];
    const float* b3  = (const float*)d_in[18];
    const float* P01 = (const float*)d_in[19];
    const float* P12 = (const float*)d_in[20];
    const float* P23 = (const float*)d_in[21];
    const float* f1w = (const float*)d_in[22];
    const float* f1b = (const float*)d_in[23];
    const float* f2w = (const float*)d_in[24];
    const float* f2b = (const float*)d_in[25];

    const int N0 = 2048, N1 = 512, N2 = 128, N3 = 64;

    float *p1, *p2, *p3;
    __nv_bfloat16 *A1h, *A1l, *A2h, *A2l, *A3h, *A3l, *Bh, *Bl;
    __nv_bfloat16 *Wt1h, *Wt1l, *Wt2h, *Wt2l;
    int *off0, *perm0, *off1, *perm1, *off2, *perm2;
    float *inv0, *inv1, *inv2;
    GETSYM(p1, g_p1); GETSYM(p2, g_p2); GETSYM(p3, g_p3);
    GETSYM(A1h, g_A1h); GETSYM(A1l, g_A1l);
    GETSYM(A2h, g_A2h); GETSYM(A2l, g_A2l);
    GETSYM(A3h, g_A3h); GETSYM(A3l, g_A3l);
    GETSYM(Bh, g_Bh); GETSYM(Bl, g_Bl);
    GETSYM(Wt1h, g_Wt1h); GETSYM(Wt1l, g_Wt1l);
    GETSYM(Wt2h, g_Wt2h); GETSYM(Wt2l, g_Wt2l);
    GETSYM(off0, g_off0); GETSYM(perm0, g_perm0);
    GETSYM(off1, g_off1); GETSYM(perm1, g_perm1);
    GETSYM(off2, g_off2); GETSYM(perm2, g_perm2);
    GETSYM(inv0, g_inv0); GETSYM(inv1, g_inv1); GETSYM(inv2, g_inv2);

    const int SMEM_GEMM = 98304;
    cudaFuncSetAttribute(mma_gemm_kernel, cudaFuncAttributeMaxDynamicSharedMemorySize,
                         SMEM_GEMM);
    const int SMEM_GEMM64 = 65536;
    cudaFuncSetAttribute(mma_gemm64_kernel, cudaFuncAttributeMaxDynamicSharedMemorySize,
                         SMEM_GEMM64);
    // cat-only dynamic smem (Wt loaded from global): 2*K4*400 + COUT*4
    const int SMEM_F1 = 2 * 64 * 400 + 32 * 4;    // ~50.1KB -> 4 blocks/SM
    const int SMEM_F2 = 2 * 128 * 400 + 64 * 4;   // ~100.3KB -> 2 blocks/SM
    cudaFuncSetAttribute((const void*)gcnf_kernel<16, 32>,
                         cudaFuncAttributeMaxDynamicSharedMemorySize, SMEM_F1);
    cudaFuncSetAttribute((const void*)gcnf_kernel<32, 64>,
                         cudaFuncAttributeMaxDynamicSharedMemorySize, SMEM_F2);
    const int SMEM_HEAD = (8192 + 8192 + 128 + 64 + 12800) * 4;
    cudaFuncSetAttribute(head_kernel, cudaFuncAttributeMaxDynamicSharedMemorySize,
                         SMEM_HEAD);

    // ---- setup: CSR (3 blocks) + splitA + Wt, one launch ----
    const long SPLIT_TOT = 512L * 2048 + 128 * 512 + 128 * 128 + 32 * 64 + 2 * 64 * 64;
    setup_kernel<<<3 + (int)((SPLIT_TOT + 1023) / 1024), 1024>>>(
        ei0, ei1, ei2, off0, perm0, inv0, off1, perm1, inv1, off2, perm2, inv2,
        P01, P12, P23, A1h, A1l, A2h, A2l, A3h, A3l,
        Wk2, Wr2, Wk3, Wr3, Wt1h, Wt1l, Wt2h, Wt2l);

    // ---- level 0->1 GCN ----
    gcn1_kernel<<<N0, 256>>>(x, ea0, A1, Wk1, Wr1, b1, ei0, off0, perm0, inv0, Bh, Bl);

    // ---- pool1: M=512, K=2048, F=3200 ----
    mma_gemm_kernel<<<dim3(3200 / 64, 512 / 128, 2), 256, SMEM_GEMM>>>(
        A1h, A1l, Bh, Bl, p1, 512, 2048, 3200);

    // ---- level 1->2 GCN (scalar gather + tensor-core combine) ----
    gcnf_kernel<16, 32><<<dim3(N1, 2), 256, SMEM_F1>>>(
        p1, ea1, A2, Wt1h, Wt1l, b2, ei1, off1, perm1, inv1, Bh, Bl, N1);

    // ---- pool2: M=128, K=512, F=6400 ----
    mma_gemm_kernel<<<dim3(6400 / 64, 1, 2), 256, SMEM_GEMM>>>(
        A2h, A2l, Bh, Bl, p2, 128, 512, 6400);

    // ---- level 2->3 GCN ----
    gcnf_kernel<32, 64><<<dim3(N2, 2), 256, SMEM_F2>>>(
        p2, ea2, A3, Wt2h, Wt2l, b3, ei2, off2, perm2, inv2, Bh, Bl, N2);

    // ---- pool3: M=64 (no padding waste), K=128, F=12800; single wave ----
    mma_gemm64_kernel<<<dim3(12800 / 64, 1, 2), 256, SMEM_GEMM64>>>(
        A3h, A3l, Bh, Bl, p3, 128, 12800);

    // ---- fused head ----
    head_kernel<<<dim3(N3, 2), 256, SMEM_HEAD>>>(
        p3, f1w, f1b, f2w, f2b, (float*)d_out, N3);
}